// round 12
// baseline (speedup 1.0000x reference)
#include <cuda_runtime.h>
#include <cuda_bf16.h>
#include <cstdint>

#define B_ 8
#define C_ 256
#define L_ 2048
#define D_ 32
#define LOG2E 1.4426950408889634f

// scratch projections (all bf16; q pre-scaled by log2(e))
__device__ __nv_bfloat16 g_q[(size_t)B_ * L_ * D_];   // [b][l][32] bf16
__device__ __nv_bfloat16 g_k[(size_t)B_ * L_ * D_];   // [b][l][32] bf16
__device__ __nv_bfloat16 g_v[(size_t)B_ * C_ * L_];   // [b][c][l]  bf16

// ---------------------------------------------------------------------------
// helpers
// ---------------------------------------------------------------------------
__device__ __forceinline__ uint32_t smem_u32(const void* p) {
    uint32_t a;
    asm("{ .reg .u64 t; cvta.to.shared.u64 t, %1; cvt.u32.u64 %0, t; }" : "=r"(a) : "l"(p));
    return a;
}
#define CP16(dst, src) \
    asm volatile("cp.async.cg.shared.global [%0], [%1], 16;" :: "r"(dst), "l"(src))
#define CP_COMMIT() asm volatile("cp.async.commit_group;")
#define CP_WAIT(n)  asm volatile("cp.async.wait_group %0;" :: "n"(n))

#define CVT_BF16X2_F32(result, a, b) \
    asm("cvt.rn.satfinite.bf16x2.f32 %0, %1, %2;" : "=r"(result) : "f"(b), "f"(a))

#define EX2F(d, s) asm("ex2.approx.f32 %0, %1;" : "=f"(d) : "f"(s))

#define STS32(addr, val) \
    asm volatile("st.shared.b32 [%0], %1;" :: "r"(addr), "r"(val) : "memory")

#define NAMED_BAR(id, cnt) \
    asm volatile("bar.sync %0, %1;" :: "r"(id), "r"(cnt) : "memory")

#define LDMATRIX_X4(r0, r1, r2, r3, addr) \
    asm volatile("ldmatrix.sync.aligned.m8n8.x4.shared.b16 {%0,%1,%2,%3}, [%4];" \
        : "=r"(r0), "=r"(r1), "=r"(r2), "=r"(r3) : "r"(addr))

#define MMA_TF32(d0,d1,d2,d3,a0,a1,a2,a3,b0,b1) \
    asm volatile("mma.sync.aligned.m16n8k8.row.col.f32.tf32.tf32.f32 " \
        "{%0,%1,%2,%3}, {%4,%5,%6,%7}, {%8,%9}, {%0,%1,%2,%3};" \
        : "+f"(d0), "+f"(d1), "+f"(d2), "+f"(d3) \
        : "r"(a0), "r"(a1), "r"(a2), "r"(a3), "r"(b0), "r"(b1))

#define MMA_BF16(d0,d1,d2,d3,a0,a1,a2,a3,b0,b1) \
    asm volatile("mma.sync.aligned.m16n8k16.row.col.f32.bf16.bf16.f32 " \
        "{%0,%1,%2,%3}, {%4,%5,%6,%7}, {%8,%9}, {%0,%1,%2,%3};" \
        : "+f"(d0), "+f"(d1), "+f"(d2), "+f"(d3) \
        : "r"(a0), "r"(a1), "r"(a2), "r"(a3), "r"(b0), "r"(b1))

// ---------------------------------------------------------------------------
// Kernel 1: QKV projection via tf32 mma.sync (raw-bit tf32 operands).
// Block: 64 r x 128 l, 256 threads = 8 warps (4 m-tiles x 2 l-halves of 64).
// Grid (16, 5, 8) = 640 blocks, 3 blocks/SM.
// q (scaled by log2e), k, v all written as bf16.
// ---------------------------------------------------------------------------
#define PW_STR 36
#define PX_STR 136
#define PW_BYTES (64 * PW_STR * 4)        // 9216
#define PX_BYTES (32 * PX_STR * 4)        // 17408
#define PSW_OFF  0
#define PSX_OFF  (2 * PW_BYTES)           // 18432
#define SMEM_PROJ (PSX_OFF + 2 * PX_BYTES) // 53248

__global__ __launch_bounds__(256, 3) void proj_kernel(
    const float* __restrict__ x,
    const float* __restrict__ Wq, const float* __restrict__ bq,
    const float* __restrict__ Wk, const float* __restrict__ bk,
    const float* __restrict__ Wv, const float* __restrict__ bv)
{
    extern __shared__ char smem[];
    const uint32_t sb = smem_u32(smem);
    float* sW = (float*)(smem + PSW_OFF);
    float* sX = (float*)(smem + PSX_OFF);

    const int b  = blockIdx.z;
    const int r0 = blockIdx.y * 64;
    const int l0 = blockIdx.x * 128;
    const int tid  = threadIdx.x;
    const int lane = tid & 31;
    const int w    = tid >> 5;
    const int g    = lane >> 2;
    const int t4   = lane & 3;
    const int mb   = (w & 3) * 16;
    const int lw   = (w >> 2) * 64;

    const float* xb = x + (size_t)b * C_ * L_;

    auto wrow = [&](int r) -> const float* {
        if (r < D_)          return Wq + (size_t)r * C_;
        else if (r < 2 * D_) return Wk + (size_t)(r - D_) * C_;
        else                 return Wv + (size_t)(r - 2 * D_) * C_;
    };

    {
        #pragma unroll
        for (int t = 0; t < 2; t++) {
            int idx = tid + t * 256;              // 512 = 64 rows x 8 segs
            int row = idx >> 3, seg = idx & 7;
            CP16(sb + PSW_OFF + row * (PW_STR * 4) + seg * 16,
                 wrow(r0 + row) + seg * 4);
        }
        #pragma unroll
        for (int t = 0; t < 4; t++) {
            int idx = tid + t * 256;              // 1024 = 32 rows x 32 segs
            int row = idx >> 5, seg = idx & 31;
            CP16(sb + PSX_OFF + row * (PX_STR * 4) + seg * 16,
                 xb + (size_t)row * L_ + l0 + seg * 4);
        }
        CP_COMMIT();
    }

    const int r_g  = r0 + mb + g;
    const int r_g8 = r_g + 8;
    float bias_lo, bias_hi;
    {
        auto bsel = [&](int r) -> float {
            if (r < D_)          return bq[r];
            else if (r < 2 * D_) return bk[r - D_];
            else                 return bv[r - 2 * D_];
        };
        bias_lo = bsel(r_g);
        bias_hi = bsel(r_g8);
    }
    float o[8][4];
    #pragma unroll
    for (int nt = 0; nt < 8; nt++) {
        o[nt][0] = bias_lo; o[nt][1] = bias_lo;
        o[nt][2] = bias_hi; o[nt][3] = bias_hi;
    }

    for (int ck = 0; ck < 8; ck++) {
        const int buf = ck & 1;
        CP_WAIT(0);
        __syncthreads();
        if (ck < 7) {
            const int c1 = (ck + 1) * 32;
            const int pb = (ck + 1) & 1;
            #pragma unroll
            for (int t = 0; t < 2; t++) {
                int idx = tid + t * 256;
                int row = idx >> 3, seg = idx & 7;
                CP16(sb + PSW_OFF + pb * PW_BYTES + row * (PW_STR * 4) + seg * 16,
                     wrow(r0 + row) + c1 + seg * 4);
            }
            #pragma unroll
            for (int t = 0; t < 4; t++) {
                int idx = tid + t * 256;
                int row = idx >> 5, seg = idx & 31;
                CP16(sb + PSX_OFF + pb * PX_BYTES + row * (PX_STR * 4) + seg * 16,
                     xb + (size_t)(c1 + row) * L_ + l0 + seg * 4);
            }
            CP_COMMIT();
        }
        const float* sWb = sW + buf * (64 * PW_STR);
        const float* sXb = sX + buf * (32 * PX_STR);
        #pragma unroll
        for (int s = 0; s < 4; s++) {
            uint32_t a0 = __float_as_uint(sWb[(mb + g) * PW_STR + s * 8 + t4]);
            uint32_t a1 = __float_as_uint(sWb[(mb + g + 8) * PW_STR + s * 8 + t4]);
            uint32_t a2 = __float_as_uint(sWb[(mb + g) * PW_STR + s * 8 + t4 + 4]);
            uint32_t a3 = __float_as_uint(sWb[(mb + g + 8) * PW_STR + s * 8 + t4 + 4]);
            #pragma unroll
            for (int nt = 0; nt < 8; nt++) {
                const int n = lw + nt * 8 + g;
                uint32_t b0 = __float_as_uint(sXb[(s * 8 + t4) * PX_STR + n]);
                uint32_t b1 = __float_as_uint(sXb[(s * 8 + t4 + 4) * PX_STR + n]);
                MMA_TF32(o[nt][0], o[nt][1], o[nt][2], o[nt][3],
                         a0, a1, a2, a3, b0, b1);
            }
        }
    }

    if (r_g < 2 * D_) {
        const bool isq = (r_g < D_);
        __nv_bfloat16* dst = isq ? (g_q + (size_t)b * L_ * D_)
                                 : (g_k + (size_t)b * L_ * D_);
        const float sc = isq ? LOG2E : 1.0f;
        const int d  = isq ? r_g : (r_g - D_);
        const int d8 = d + 8;
        #pragma unroll
        for (int nt = 0; nt < 8; nt++) {
            const int l = l0 + lw + nt * 8 + t4 * 2;
            dst[(size_t)l * D_ + d]        = __float2bfloat16_rn(o[nt][0] * sc);
            dst[(size_t)(l + 1) * D_ + d]  = __float2bfloat16_rn(o[nt][1] * sc);
            dst[(size_t)l * D_ + d8]       = __float2bfloat16_rn(o[nt][2] * sc);
            dst[(size_t)(l + 1) * D_ + d8] = __float2bfloat16_rn(o[nt][3] * sc);
        }
    } else {
        __nv_bfloat16* vb = g_v + (size_t)b * C_ * L_;
        const int c = r_g - 2 * D_, c8 = c + 8;
        #pragma unroll
        for (int nt = 0; nt < 8; nt++) {
            const int l = l0 + lw + nt * 8 + t4 * 2;
            uint32_t lo, hi;
            CVT_BF16X2_F32(lo, o[nt][0], o[nt][1]);
            CVT_BF16X2_F32(hi, o[nt][2], o[nt][3]);
            *(uint32_t*)&vb[(size_t)c * L_ + l]  = lo;
            *(uint32_t*)&vb[(size_t)c8 * L_ + l] = hi;
        }
    }
}

// ---------------------------------------------------------------------------
// Kernel 2: bf16 mma.sync flash attention, 32-query blocks for SM balance.
// Block: 32 q x 256 c, 256 threads = 8 warps (2 m-groups of 16q x 4 c-quarters).
// Grid (64, 8) = 512 blocks, 2/SM -> all 148 SMs carry work.
// Stage A: warp (mgrp,cq) computes S(16q x 16 keys), ex2, packs to sP.
// Stage B: O(16q x 64c) += P(16q x 64k) V(64c x 64k), P frags via ldmatrix.
// SMEM: sQ [32][80B] | sK 2x[64][80B] | sV 2x[256][144B] | sP 2x[16][144B] | sRS
// ---------------------------------------------------------------------------
#define QKROW 80
#define VROW  144
#define SQ_OFF  0
#define SK_OFF  2560
#define SKB     5120
#define SV_OFF  12800
#define SVB     36864
#define SP_OFF  86528
#define SPM     2304                   // 16 rows x 144 B per m-group
#define SRS_OFF 91136                  // 32 rows x 4 cq floats = 512 B
#define SMEM_AT 91648

__global__ __launch_bounds__(256, 2) void attn_kernel(
    const float* __restrict__ x, const float* __restrict__ gamma_p,
    float* __restrict__ out)
{
    extern __shared__ char smem[];
    const uint32_t sb = smem_u32(smem);

    const int tid  = threadIdx.x;
    const int lane = tid & 31;
    const int w    = tid >> 5;
    const int g    = lane >> 2;
    const int t4   = lane & 3;
    const int mgrp = w >> 2;           // 0/1 : q rows mgrp*16..+15 (warps 0-3 / 4-7)
    const int cq   = w & 3;            // 0..3 : c cols cq*64..+63
    const int lr   = lane & 7;
    const int l8   = (lane >> 3) & 1;
    const int l16  = (lane >> 4) & 1;

    const int b  = blockIdx.y;
    const int m0 = blockIdx.x * 32;

    const __nv_bfloat16* qg = g_q + (size_t)b * L_ * D_;
    const __nv_bfloat16* kg = g_k + (size_t)b * L_ * D_;
    const __nv_bfloat16* vg = g_v + (size_t)b * C_ * L_;

    // ---- ldmatrix / STS base addresses ----
    const uint32_t qlm  = sb + SQ_OFF + (uint32_t)(mgrp * 16 + lr + l8 * 8) * QKROW + l16 * 16;
    const uint32_t klmb = sb + SK_OFF + (uint32_t)(16 * cq + lr) * QKROW + (lane >> 3) * 16;
    const uint32_t vlmb = sb + SV_OFF + (uint32_t)(cq * 64 + l16 * 8 + lr) * VROW + l8 * 16;
    const uint32_t plm  = sb + SP_OFF + mgrp * SPM + (uint32_t)(lr + l8 * 8) * VROW + l16 * 16;
    const uint32_t psta = sb + SP_OFF + mgrp * SPM + (uint32_t)g * VROW + (16 * cq + 2 * t4) * 2;

    // ---- preload Q (32x32), K0 (64x32), V0 (256x64) ----
    {
        if (tid < 128) {
            int row = tid >> 2, seg = tid & 3;
            CP16(sb + SQ_OFF + row * QKROW + seg * 16, qg + (size_t)(m0 + row) * D_ + seg * 8);
        }
        {
            int row = tid >> 2, seg = tid & 3;
            CP16(sb + SK_OFF + row * QKROW + seg * 16, kg + (size_t)row * D_ + seg * 8);
        }
        #pragma unroll
        for (int t = 0; t < 8; t++) {
            int idx = tid + t * 256;
            int r = idx >> 3, s = idx & 7;
            CP16(sb + SV_OFF + r * VROW + s * 16, vg + (size_t)r * L_ + s * 8);
        }
        CP_COMMIT();
    }

    uint32_t qa[8];                    // A frags: [0..3] k0-15, [4..7] k16-31
    float o[8][4];                     // [ct][4] : c tiles cq*64 + ct*8
    #pragma unroll
    for (int i = 0; i < 8; i++)
        #pragma unroll
        for (int j = 0; j < 4; j++) o[i][j] = 0.f;
    float rs[2] = {0.f, 0.f};          // rows g, g+8

    for (int it = 0; it < 32; it++) {
        const int buf = it & 1;
        CP_WAIT(0);
        __syncthreads();

        if (it == 0) {
            LDMATRIX_X4(qa[0], qa[1], qa[2], qa[3], qlm);
            LDMATRIX_X4(qa[4], qa[5], qa[6], qa[7], qlm + 32);
        }

        if (it < 31) {
            const int n1 = (it + 1) * 64;
            const int pb = (it + 1) & 1;
            int row = tid >> 2, seg = tid & 3;
            CP16(sb + SK_OFF + pb * SKB + row * QKROW + seg * 16,
                 kg + (size_t)(n1 + row) * D_ + seg * 8);
            #pragma unroll
            for (int t = 0; t < 8; t++) {
                int idx = tid + t * 256;
                int r = idx >> 3, s = idx & 7;
                CP16(sb + SV_OFF + pb * SVB + r * VROW + s * 16,
                     vg + (size_t)r * L_ + n1 + s * 8);
            }
            CP_COMMIT();
        }

        const uint32_t klm = klmb + buf * SKB;
        const uint32_t vlm = vlmb + buf * SVB;

        // ---- stage A: S(16q x 16 keys of quarter cq), ex2, pack -> sP ----
        #pragma unroll
        for (int t = 0; t < 2; t++) {
            uint32_t kb0, kb1, kb2, kb3;
            LDMATRIX_X4(kb0, kb1, kb2, kb3, klm + t * (8 * QKROW));
            float d0 = 0.f, d1 = 0.f, d2 = 0.f, d3 = 0.f;
            MMA_BF16(d0, d1, d2, d3, qa[0], qa[1], qa[2], qa[3], kb0, kb1);
            MMA_BF16(d0, d1, d2, d3, qa[4], qa[5], qa[6], qa[7], kb2, kb3);
            float e0, e1, e2, e3;
            EX2F(e0, d0); EX2F(e1, d1); EX2F(e2, d2); EX2F(e3, d3);
            rs[0] += e0 + e1;
            rs[1] += e2 + e3;
            uint32_t lo, hi;
            CVT_BF16X2_F32(lo, e0, e1);
            CVT_BF16X2_F32(hi, e2, e3);
            STS32(psta + t * 16, lo);
            STS32(psta + 8 * VROW + t * 16, hi);
        }
        // per-m-group sync: P producers == P consumers == warps of this mgrp
        NAMED_BAR(1 + mgrp, 128);

        // ---- stage B: O(16q x 64c) += P Vt ----
        #pragma unroll
        for (int j = 0; j < 4; j++) {
            uint32_t a0[4];
            LDMATRIX_X4(a0[0], a0[1], a0[2], a0[3], plm + j * 32);
            #pragma unroll
            for (int cp = 0; cp < 4; cp++) {
                uint32_t v0, v1, v2, v3;
                LDMATRIX_X4(v0, v1, v2, v3, vlm + cp * (16 * VROW) + j * 32);
                MMA_BF16(o[2*cp][0], o[2*cp][1], o[2*cp][2], o[2*cp][3],
                         a0[0], a0[1], a0[2], a0[3], v0, v1);
                MMA_BF16(o[2*cp+1][0], o[2*cp+1][1], o[2*cp+1][2], o[2*cp+1][3],
                         a0[0], a0[1], a0[2], a0[3], v2, v3);
            }
        }
    }

    // ---- rowsums: t4 shfl reduce, then combine 4 c-quarters via smem ----
    #pragma unroll
    for (int r = 0; r < 2; r++) {
        rs[r] += __shfl_xor_sync(0xFFFFFFFFu, rs[r], 1);
        rs[r] += __shfl_xor_sync(0xFFFFFFFFu, rs[r], 2);
    }
    float* sRS = (float*)(smem + SRS_OFF);
    if (t4 == 0) {
        sRS[(mgrp * 16 + g) * 4 + cq]     = rs[0];
        sRS[(mgrp * 16 + g + 8) * 4 + cq] = rs[1];
    }
    __syncthreads();

    const float gam = gamma_p[0];
    float inv[2];
    #pragma unroll
    for (int r = 0; r < 2; r++) {
        const int row = mgrp * 16 + r * 8 + g;
        inv[r] = gam / (sRS[row * 4] + sRS[row * 4 + 1] + sRS[row * 4 + 2] + sRS[row * 4 + 3]);
    }

    const float* xb = x + (size_t)b * C_ * L_;
    float* ob = out + (size_t)b * C_ * L_;
    const int mA = m0 + mgrp * 16 + g;
    const int mB = mA + 8;
    const float iA = inv[0], iB = inv[1];
    #pragma unroll
    for (int ct = 0; ct < 8; ct++) {
        const int c0 = cq * 64 + ct * 8 + t4 * 2;
        ob[(size_t)c0 * L_ + mA]       = o[ct][0] * iA + xb[(size_t)c0 * L_ + mA];
        ob[(size_t)(c0 + 1) * L_ + mA] = o[ct][1] * iA + xb[(size_t)(c0 + 1) * L_ + mA];
        ob[(size_t)c0 * L_ + mB]       = o[ct][2] * iB + xb[(size_t)c0 * L_ + mB];
        ob[(size_t)(c0 + 1) * L_ + mB] = o[ct][3] * iB + xb[(size_t)(c0 + 1) * L_ + mB];
    }
}

// ---------------------------------------------------------------------------
extern "C" void kernel_launch(void* const* d_in, const int* in_sizes, int n_in,
                              void* d_out, int out_size)
{
    (void)in_sizes; (void)n_in; (void)out_size;
    const float* x     = (const float*)d_in[0];
    const float* Wq    = (const float*)d_in[1];
    const float* bq    = (const float*)d_in[2];
    const float* Wk    = (const float*)d_in[3];
    const float* bk    = (const float*)d_in[4];
    const float* Wv    = (const float*)d_in[5];
    const float* bv    = (const float*)d_in[6];
    const float* gamma = (const float*)d_in[7];
    float* out = (float*)d_out;

    cudaFuncSetAttribute(proj_kernel, cudaFuncAttributeMaxDynamicSharedMemorySize, SMEM_PROJ);
    proj_kernel<<<dim3(L_ / 128, 5, B_), 256, SMEM_PROJ>>>(x, Wq, bq, Wk, bk, Wv, bv);

    cudaFuncSetAttribute(attn_kernel, cudaFuncAttributeMaxDynamicSharedMemorySize, SMEM_AT);
    attn_kernel<<<dim3(L_ / 32, B_), 256, SMEM_AT>>>(x, gamma, out);
}

// round 13
// speedup vs baseline: 1.3103x; 1.3103x over previous
#include <cuda_runtime.h>
#include <cuda_bf16.h>
#include <cstdint>

#define B_ 8
#define C_ 256
#define L_ 2048
#define D_ 32
#define LOG2E 1.4426950408889634f

// scratch projections (all bf16; q pre-scaled by log2(e))
__device__ __nv_bfloat16 g_q[(size_t)B_ * L_ * D_];   // [b][l][32] bf16
__device__ __nv_bfloat16 g_k[(size_t)B_ * L_ * D_];   // [b][l][32] bf16
__device__ __nv_bfloat16 g_v[(size_t)B_ * C_ * L_];   // [b][c][l]  bf16

// ---------------------------------------------------------------------------
// helpers
// ---------------------------------------------------------------------------
__device__ __forceinline__ uint32_t smem_u32(const void* p) {
    uint32_t a;
    asm("{ .reg .u64 t; cvta.to.shared.u64 t, %1; cvt.u32.u64 %0, t; }" : "=r"(a) : "l"(p));
    return a;
}
#define CP16(dst, src) \
    asm volatile("cp.async.cg.shared.global [%0], [%1], 16;" :: "r"(dst), "l"(src))
#define CP_COMMIT() asm volatile("cp.async.commit_group;")
#define CP_WAIT(n)  asm volatile("cp.async.wait_group %0;" :: "n"(n))

#define CVT_BF16X2_F32(result, a, b) \
    asm("cvt.rn.satfinite.bf16x2.f32 %0, %1, %2;" : "=r"(result) : "f"(b), "f"(a))

#define EX2F(d, s) asm("ex2.approx.f32 %0, %1;" : "=f"(d) : "f"(s))

#define STS32(addr, val) \
    asm volatile("st.shared.b32 [%0], %1;" :: "r"(addr), "r"(val) : "memory")

#define NAMED_BAR(id, cnt) \
    asm volatile("bar.sync %0, %1;" :: "r"(id), "r"(cnt) : "memory")

#define LDMATRIX_X4(r0, r1, r2, r3, addr) \
    asm volatile("ldmatrix.sync.aligned.m8n8.x4.shared.b16 {%0,%1,%2,%3}, [%4];" \
        : "=r"(r0), "=r"(r1), "=r"(r2), "=r"(r3) : "r"(addr))

#define MMA_TF32(d0,d1,d2,d3,a0,a1,a2,a3,b0,b1) \
    asm volatile("mma.sync.aligned.m16n8k8.row.col.f32.tf32.tf32.f32 " \
        "{%0,%1,%2,%3}, {%4,%5,%6,%7}, {%8,%9}, {%0,%1,%2,%3};" \
        : "+f"(d0), "+f"(d1), "+f"(d2), "+f"(d3) \
        : "r"(a0), "r"(a1), "r"(a2), "r"(a3), "r"(b0), "r"(b1))

#define MMA_BF16(d0,d1,d2,d3,a0,a1,a2,a3,b0,b1) \
    asm volatile("mma.sync.aligned.m16n8k16.row.col.f32.bf16.bf16.f32 " \
        "{%0,%1,%2,%3}, {%4,%5,%6,%7}, {%8,%9}, {%0,%1,%2,%3};" \
        : "+f"(d0), "+f"(d1), "+f"(d2), "+f"(d3) \
        : "r"(a0), "r"(a1), "r"(a2), "r"(a3), "r"(b0), "r"(b1))

// ---------------------------------------------------------------------------
// Kernel 1: QKV projection via tf32 mma.sync (raw-bit tf32 operands).
// Block: 64 r x 128 l, 256 threads = 8 warps (4 m-tiles x 2 l-halves of 64).
// Grid (16, 5, 8) = 640 blocks, 3 blocks/SM.  [round-12 proj, ~23 µs measured]
// q (scaled by log2e), k, v all written as bf16.
// ---------------------------------------------------------------------------
#define PW_STR 36
#define PX_STR 136
#define PW_BYTES (64 * PW_STR * 4)        // 9216
#define PX_BYTES (32 * PX_STR * 4)        // 17408
#define PSW_OFF  0
#define PSX_OFF  (2 * PW_BYTES)           // 18432
#define SMEM_PROJ (PSX_OFF + 2 * PX_BYTES) // 53248

__global__ __launch_bounds__(256, 3) void proj_kernel(
    const float* __restrict__ x,
    const float* __restrict__ Wq, const float* __restrict__ bq,
    const float* __restrict__ Wk, const float* __restrict__ bk,
    const float* __restrict__ Wv, const float* __restrict__ bv)
{
    extern __shared__ char smem[];
    const uint32_t sb = smem_u32(smem);
    float* sW = (float*)(smem + PSW_OFF);
    float* sX = (float*)(smem + PSX_OFF);

    const int b  = blockIdx.z;
    const int r0 = blockIdx.y * 64;
    const int l0 = blockIdx.x * 128;
    const int tid  = threadIdx.x;
    const int lane = tid & 31;
    const int w    = tid >> 5;
    const int g    = lane >> 2;
    const int t4   = lane & 3;
    const int mb   = (w & 3) * 16;
    const int lw   = (w >> 2) * 64;

    const float* xb = x + (size_t)b * C_ * L_;

    auto wrow = [&](int r) -> const float* {
        if (r < D_)          return Wq + (size_t)r * C_;
        else if (r < 2 * D_) return Wk + (size_t)(r - D_) * C_;
        else                 return Wv + (size_t)(r - 2 * D_) * C_;
    };

    {
        #pragma unroll
        for (int t = 0; t < 2; t++) {
            int idx = tid + t * 256;              // 512 = 64 rows x 8 segs
            int row = idx >> 3, seg = idx & 7;
            CP16(sb + PSW_OFF + row * (PW_STR * 4) + seg * 16,
                 wrow(r0 + row) + seg * 4);
        }
        #pragma unroll
        for (int t = 0; t < 4; t++) {
            int idx = tid + t * 256;              // 1024 = 32 rows x 32 segs
            int row = idx >> 5, seg = idx & 31;
            CP16(sb + PSX_OFF + row * (PX_STR * 4) + seg * 16,
                 xb + (size_t)row * L_ + l0 + seg * 4);
        }
        CP_COMMIT();
    }

    const int r_g  = r0 + mb + g;
    const int r_g8 = r_g + 8;
    float bias_lo, bias_hi;
    {
        auto bsel = [&](int r) -> float {
            if (r < D_)          return bq[r];
            else if (r < 2 * D_) return bk[r - D_];
            else                 return bv[r - 2 * D_];
        };
        bias_lo = bsel(r_g);
        bias_hi = bsel(r_g8);
    }
    float o[8][4];
    #pragma unroll
    for (int nt = 0; nt < 8; nt++) {
        o[nt][0] = bias_lo; o[nt][1] = bias_lo;
        o[nt][2] = bias_hi; o[nt][3] = bias_hi;
    }

    for (int ck = 0; ck < 8; ck++) {
        const int buf = ck & 1;
        CP_WAIT(0);
        __syncthreads();
        if (ck < 7) {
            const int c1 = (ck + 1) * 32;
            const int pb = (ck + 1) & 1;
            #pragma unroll
            for (int t = 0; t < 2; t++) {
                int idx = tid + t * 256;
                int row = idx >> 3, seg = idx & 7;
                CP16(sb + PSW_OFF + pb * PW_BYTES + row * (PW_STR * 4) + seg * 16,
                     wrow(r0 + row) + c1 + seg * 4);
            }
            #pragma unroll
            for (int t = 0; t < 4; t++) {
                int idx = tid + t * 256;
                int row = idx >> 5, seg = idx & 31;
                CP16(sb + PSX_OFF + pb * PX_BYTES + row * (PX_STR * 4) + seg * 16,
                     xb + (size_t)(c1 + row) * L_ + l0 + seg * 4);
            }
            CP_COMMIT();
        }
        const float* sWb = sW + buf * (64 * PW_STR);
        const float* sXb = sX + buf * (32 * PX_STR);
        #pragma unroll
        for (int s = 0; s < 4; s++) {
            uint32_t a0 = __float_as_uint(sWb[(mb + g) * PW_STR + s * 8 + t4]);
            uint32_t a1 = __float_as_uint(sWb[(mb + g + 8) * PW_STR + s * 8 + t4]);
            uint32_t a2 = __float_as_uint(sWb[(mb + g) * PW_STR + s * 8 + t4 + 4]);
            uint32_t a3 = __float_as_uint(sWb[(mb + g + 8) * PW_STR + s * 8 + t4 + 4]);
            #pragma unroll
            for (int nt = 0; nt < 8; nt++) {
                const int n = lw + nt * 8 + g;
                uint32_t b0 = __float_as_uint(sXb[(s * 8 + t4) * PX_STR + n]);
                uint32_t b1 = __float_as_uint(sXb[(s * 8 + t4 + 4) * PX_STR + n]);
                MMA_TF32(o[nt][0], o[nt][1], o[nt][2], o[nt][3],
                         a0, a1, a2, a3, b0, b1);
            }
        }
    }

    if (r_g < 2 * D_) {
        const bool isq = (r_g < D_);
        __nv_bfloat16* dst = isq ? (g_q + (size_t)b * L_ * D_)
                                 : (g_k + (size_t)b * L_ * D_);
        const float sc = isq ? LOG2E : 1.0f;
        const int d  = isq ? r_g : (r_g - D_);
        const int d8 = d + 8;
        #pragma unroll
        for (int nt = 0; nt < 8; nt++) {
            const int l = l0 + lw + nt * 8 + t4 * 2;
            dst[(size_t)l * D_ + d]        = __float2bfloat16_rn(o[nt][0] * sc);
            dst[(size_t)(l + 1) * D_ + d]  = __float2bfloat16_rn(o[nt][1] * sc);
            dst[(size_t)l * D_ + d8]       = __float2bfloat16_rn(o[nt][2] * sc);
            dst[(size_t)(l + 1) * D_ + d8] = __float2bfloat16_rn(o[nt][3] * sc);
        }
    } else {
        __nv_bfloat16* vb = g_v + (size_t)b * C_ * L_;
        const int c = r_g - 2 * D_, c8 = c + 8;
        #pragma unroll
        for (int nt = 0; nt < 8; nt++) {
            const int l = l0 + lw + nt * 8 + t4 * 2;
            uint32_t lo, hi;
            CVT_BF16X2_F32(lo, o[nt][0], o[nt][1]);
            CVT_BF16X2_F32(hi, o[nt][2], o[nt][3]);
            *(uint32_t*)&vb[(size_t)c * L_ + l]  = lo;
            *(uint32_t*)&vb[(size_t)c8 * L_ + l] = hi;
        }
    }
}

// ---------------------------------------------------------------------------
// Kernel 2: bf16 mma.sync flash attention [round-11 attn, 88.1 µs measured].
// 64 q x 256 c blocks, 256 threads = 8 warps (2 m-groups x 4 c-quarters),
// S dedup + per-m-group named barrier between stage A and stage B.
// SMEM: sQ [64][80B] | sK 2x[64][80B] | sV 2x[256][144B] | sP 2x[32][144B] | sRS
// ---------------------------------------------------------------------------
#define QKROW 80
#define VROW  144
#define SQ_OFF  0
#define SK_OFF  5120
#define SKB     5120
#define SV_OFF  15360
#define SVB     36864
#define SP_OFF  89088
#define SPM     4608                   // 32 rows x 144 B per m-group
#define SRS_OFF 98304                  // 64 rows x 4 cq floats = 1024 B
#define SMEM_AT 99328

__global__ __launch_bounds__(256, 2) void attn_kernel(
    const float* __restrict__ x, const float* __restrict__ gamma_p,
    float* __restrict__ out)
{
    extern __shared__ char smem[];
    const uint32_t sb = smem_u32(smem);

    const int tid  = threadIdx.x;
    const int lane = tid & 31;
    const int w    = tid >> 5;
    const int g    = lane >> 2;
    const int t4   = lane & 3;
    const int mgrp = w >> 2;           // 0/1 : q rows mgrp*32..+31 (warps 0-3 / 4-7)
    const int cq   = w & 3;            // 0..3 : c cols cq*64..+63
    const int lr   = lane & 7;
    const int l8   = (lane >> 3) & 1;
    const int l16  = (lane >> 4) & 1;

    const int b  = blockIdx.y;
    const int m0 = blockIdx.x * 64;

    const __nv_bfloat16* qg = g_q + (size_t)b * L_ * D_;
    const __nv_bfloat16* kg = g_k + (size_t)b * L_ * D_;
    const __nv_bfloat16* vg = g_v + (size_t)b * C_ * L_;

    // ---- ldmatrix / STS base addresses ----
    const uint32_t qlm  = sb + SQ_OFF + (uint32_t)(mgrp * 32 + lr + l8 * 8) * QKROW + l16 * 16;
    const uint32_t klmb = sb + SK_OFF + (uint32_t)(16 * cq + lr) * QKROW + (lane >> 3) * 16;
    const uint32_t vlmb = sb + SV_OFF + (uint32_t)(cq * 64 + l16 * 8 + lr) * VROW + l8 * 16;
    const uint32_t plm  = sb + SP_OFF + mgrp * SPM + (uint32_t)(lr + l8 * 8) * VROW + l16 * 16;
    const uint32_t psta = sb + SP_OFF + mgrp * SPM + (uint32_t)g * VROW + (16 * cq + 2 * t4) * 2;

    // ---- preload Q (64x32), K0, V0 ----
    {
        int row = tid >> 2, seg = tid & 3;
        CP16(sb + SQ_OFF + row * QKROW + seg * 16, qg + (size_t)(m0 + row) * D_ + seg * 8);
        CP16(sb + SK_OFF + row * QKROW + seg * 16, kg + (size_t)row * D_ + seg * 8);
        #pragma unroll
        for (int t = 0; t < 8; t++) {
            int idx = tid + t * 256;
            int r = idx >> 3, s = idx & 7;
            CP16(sb + SV_OFF + r * VROW + s * 16, vg + (size_t)r * L_ + s * 8);
        }
        CP_COMMIT();
    }

    uint32_t qa[2][8];                 // 2 m-tiles x (k0-15: 4, k16-31: 4)
    float o[16][4];                    // [i*8 + ct2][4]
    #pragma unroll
    for (int i = 0; i < 16; i++)
        #pragma unroll
        for (int j = 0; j < 4; j++) o[i][j] = 0.f;
    float rs[4] = {0.f, 0.f, 0.f, 0.f};   // rows: i0 g, i0 g+8, i1 g, i1 g+8

    for (int it = 0; it < 32; it++) {
        const int buf = it & 1;
        CP_WAIT(0);
        __syncthreads();

        if (it == 0) {
            #pragma unroll
            for (int i = 0; i < 2; i++) {
                LDMATRIX_X4(qa[i][0], qa[i][1], qa[i][2], qa[i][3],
                            qlm + i * (16 * QKROW));
                LDMATRIX_X4(qa[i][4], qa[i][5], qa[i][6], qa[i][7],
                            qlm + i * (16 * QKROW) + 32);
            }
        }

        if (it < 31) {
            const int n1 = (it + 1) * 64;
            const int pb = (it + 1) & 1;
            int row = tid >> 2, seg = tid & 3;
            CP16(sb + SK_OFF + pb * SKB + row * QKROW + seg * 16,
                 kg + (size_t)(n1 + row) * D_ + seg * 8);
            #pragma unroll
            for (int t = 0; t < 8; t++) {
                int idx = tid + t * 256;
                int r = idx >> 3, s = idx & 7;
                CP16(sb + SV_OFF + pb * SVB + r * VROW + s * 16,
                     vg + (size_t)r * L_ + n1 + s * 8);
            }
            CP_COMMIT();
        }

        const uint32_t klm = klmb + buf * SKB;
        const uint32_t vlm = vlmb + buf * SVB;

        // ---- stage A: S(32q x 16 keys of quarter cq), ex2, pack -> sP ----
        #pragma unroll
        for (int t = 0; t < 2; t++) {
            uint32_t kb0, kb1, kb2, kb3;
            LDMATRIX_X4(kb0, kb1, kb2, kb3, klm + t * (8 * QKROW));
            #pragma unroll
            for (int i = 0; i < 2; i++) {
                float d0 = 0.f, d1 = 0.f, d2 = 0.f, d3 = 0.f;
                MMA_BF16(d0, d1, d2, d3,
                         qa[i][0], qa[i][1], qa[i][2], qa[i][3], kb0, kb1);
                MMA_BF16(d0, d1, d2, d3,
                         qa[i][4], qa[i][5], qa[i][6], qa[i][7], kb2, kb3);
                float e0, e1, e2, e3;
                EX2F(e0, d0); EX2F(e1, d1); EX2F(e2, d2); EX2F(e3, d3);
                rs[2 * i]     += e0 + e1;
                rs[2 * i + 1] += e2 + e3;
                uint32_t lo, hi;
                CVT_BF16X2_F32(lo, e0, e1);
                CVT_BF16X2_F32(hi, e2, e3);
                STS32(psta + i * (16 * VROW) + t * 16, lo);
                STS32(psta + i * (16 * VROW) + 8 * VROW + t * 16, hi);
            }
        }
        // per-m-group sync: P producers == P consumers == warps of this mgrp
        NAMED_BAR(1 + mgrp, 128);

        // ---- stage B: O += P Vt (P frags from sP, V frags shared by 2 m-tiles) ----
        #pragma unroll
        for (int j = 0; j < 4; j++) {
            uint32_t a0[4], a1[4];
            LDMATRIX_X4(a0[0], a0[1], a0[2], a0[3], plm + j * 32);
            LDMATRIX_X4(a1[0], a1[1], a1[2], a1[3], plm + 16 * VROW + j * 32);
            #pragma unroll
            for (int cp = 0; cp < 4; cp++) {
                uint32_t v0, v1, v2, v3;
                LDMATRIX_X4(v0, v1, v2, v3, vlm + cp * (16 * VROW) + j * 32);
                MMA_BF16(o[2*cp][0], o[2*cp][1], o[2*cp][2], o[2*cp][3],
                         a0[0], a0[1], a0[2], a0[3], v0, v1);
                MMA_BF16(o[2*cp+1][0], o[2*cp+1][1], o[2*cp+1][2], o[2*cp+1][3],
                         a0[0], a0[1], a0[2], a0[3], v2, v3);
                MMA_BF16(o[8+2*cp][0], o[8+2*cp][1], o[8+2*cp][2], o[8+2*cp][3],
                         a1[0], a1[1], a1[2], a1[3], v0, v1);
                MMA_BF16(o[8+2*cp+1][0], o[8+2*cp+1][1], o[8+2*cp+1][2], o[8+2*cp+1][3],
                         a1[0], a1[1], a1[2], a1[3], v2, v3);
            }
        }
    }

    // ---- rowsums: t4 shfl reduce, then combine 4 c-quarters via smem ----
    #pragma unroll
    for (int r = 0; r < 4; r++) {
        rs[r] += __shfl_xor_sync(0xFFFFFFFFu, rs[r], 1);
        rs[r] += __shfl_xor_sync(0xFFFFFFFFu, rs[r], 2);
    }
    float* sRS = (float*)(smem + SRS_OFF);
    if (t4 == 0) {
        sRS[(mgrp * 32 + g) * 4 + cq]           = rs[0];
        sRS[(mgrp * 32 + g + 8) * 4 + cq]       = rs[1];
        sRS[(mgrp * 32 + 16 + g) * 4 + cq]      = rs[2];
        sRS[(mgrp * 32 + 16 + g + 8) * 4 + cq]  = rs[3];
    }
    __syncthreads();

    const float gam = gamma_p[0];
    float inv[4];
    #pragma unroll
    for (int r = 0; r < 4; r++) {
        const int row = mgrp * 32 + 16 * (r >> 1) + (r & 1) * 8 + g;
        inv[r] = gam / (sRS[row * 4] + sRS[row * 4 + 1] + sRS[row * 4 + 2] + sRS[row * 4 + 3]);
    }

    const float* xb = x + (size_t)b * C_ * L_;
    float* ob = out + (size_t)b * C_ * L_;
    #pragma unroll
    for (int i = 0; i < 2; i++) {
        const int mA = m0 + mgrp * 32 + 16 * i + g;
        const int mB = mA + 8;
        const float iA = inv[2 * i], iB = inv[2 * i + 1];
        #pragma unroll
        for (int ct = 0; ct < 8; ct++) {
            const int c0 = cq * 64 + ct * 8 + t4 * 2;
            const int oi = i * 8 + ct;
            ob[(size_t)c0 * L_ + mA]       = o[oi][0] * iA + xb[(size_t)c0 * L_ + mA];
            ob[(size_t)(c0 + 1) * L_ + mA] = o[oi][1] * iA + xb[(size_t)(c0 + 1) * L_ + mA];
            ob[(size_t)c0 * L_ + mB]       = o[oi][2] * iB + xb[(size_t)c0 * L_ + mB];
            ob[(size_t)(c0 + 1) * L_ + mB] = o[oi][3] * iB + xb[(size_t)(c0 + 1) * L_ + mB];
        }
    }
}

// ---------------------------------------------------------------------------
extern "C" void kernel_launch(void* const* d_in, const int* in_sizes, int n_in,
                              void* d_out, int out_size)
{
    (void)in_sizes; (void)n_in; (void)out_size;
    const float* x     = (const float*)d_in[0];
    const float* Wq    = (const float*)d_in[1];
    const float* bq    = (const float*)d_in[2];
    const float* Wk    = (const float*)d_in[3];
    const float* bk    = (const float*)d_in[4];
    const float* Wv    = (const float*)d_in[5];
    const float* bv    = (const float*)d_in[6];
    const float* gamma = (const float*)d_in[7];
    float* out = (float*)d_out;

    cudaFuncSetAttribute(proj_kernel, cudaFuncAttributeMaxDynamicSharedMemorySize, SMEM_PROJ);
    proj_kernel<<<dim3(L_ / 128, 5, B_), 256, SMEM_PROJ>>>(x, Wq, bq, Wk, bk, Wv, bv);

    cudaFuncSetAttribute(attn_kernel, cudaFuncAttributeMaxDynamicSharedMemorySize, SMEM_AT);
    attn_kernel<<<dim3(L_ / 64, B_), 256, SMEM_AT>>>(x, gamma, out);
}

// round 14
// speedup vs baseline: 1.3292x; 1.0145x over previous
#include <cuda_runtime.h>
#include <cuda_bf16.h>
#include <cstdint>

#define B_ 8
#define C_ 256
#define L_ 2048
#define D_ 32
#define LOG2E 1.4426950408889634f

// scratch projections (all bf16; q pre-scaled by log2(e))
__device__ __nv_bfloat16 g_q[(size_t)B_ * L_ * D_];   // [b][l][32] bf16
__device__ __nv_bfloat16 g_k[(size_t)B_ * L_ * D_];   // [b][l][32] bf16
__device__ __nv_bfloat16 g_v[(size_t)B_ * C_ * L_];   // [b][c][l]  bf16

// ---------------------------------------------------------------------------
// helpers
// ---------------------------------------------------------------------------
__device__ __forceinline__ uint32_t smem_u32(const void* p) {
    uint32_t a;
    asm("{ .reg .u64 t; cvta.to.shared.u64 t, %1; cvt.u32.u64 %0, t; }" : "=r"(a) : "l"(p));
    return a;
}
#define CP16(dst, src) \
    asm volatile("cp.async.cg.shared.global [%0], [%1], 16;" :: "r"(dst), "l"(src))
#define CP_COMMIT() asm volatile("cp.async.commit_group;")
#define CP_WAIT(n)  asm volatile("cp.async.wait_group %0;" :: "n"(n))

#define CVT_BF16X2_F32(result, a, b) \
    asm("cvt.rn.satfinite.bf16x2.f32 %0, %1, %2;" : "=r"(result) : "f"(b), "f"(a))

#define EX2F(d, s) asm("ex2.approx.f32 %0, %1;" : "=f"(d) : "f"(s))

#define STS32(addr, val) \
    asm volatile("st.shared.b32 [%0], %1;" :: "r"(addr), "r"(val) : "memory")

#define NAMED_BAR(id, cnt) \
    asm volatile("bar.sync %0, %1;" :: "r"(id), "r"(cnt) : "memory")

#define LDMATRIX_X4(r0, r1, r2, r3, addr) \
    asm volatile("ldmatrix.sync.aligned.m8n8.x4.shared.b16 {%0,%1,%2,%3}, [%4];" \
        : "=r"(r0), "=r"(r1), "=r"(r2), "=r"(r3) : "r"(addr))

#define MMA_TF32(d0,d1,d2,d3,a0,a1,a2,a3,b0,b1) \
    asm volatile("mma.sync.aligned.m16n8k8.row.col.f32.tf32.tf32.f32 " \
        "{%0,%1,%2,%3}, {%4,%5,%6,%7}, {%8,%9}, {%0,%1,%2,%3};" \
        : "+f"(d0), "+f"(d1), "+f"(d2), "+f"(d3) \
        : "r"(a0), "r"(a1), "r"(a2), "r"(a3), "r"(b0), "r"(b1))

#define MMA_BF16(d0,d1,d2,d3,a0,a1,a2,a3,b0,b1) \
    asm volatile("mma.sync.aligned.m16n8k16.row.col.f32.bf16.bf16.f32 " \
        "{%0,%1,%2,%3}, {%4,%5,%6,%7}, {%8,%9}, {%0,%1,%2,%3};" \
        : "+f"(d0), "+f"(d1), "+f"(d2), "+f"(d3) \
        : "r"(a0), "r"(a1), "r"(a2), "r"(a3), "r"(b0), "r"(b1))

// ---------------------------------------------------------------------------
// Kernel 1: QKV projection via tf32 mma.sync (raw-bit tf32 operands).
// Block: 64 r x 128 l, 256 threads = 8 warps (4 m-tiles x 2 l-halves of 64).
// Grid (16, 5, 8) = 640 blocks, 3 blocks/SM.
// X tiles: 3-stage cp.async ring (prefetch distance 2); W tiles: 2-stage.
// Per-iter commit order: {W(ck+1)} then {X(ck+2)} (empty when exhausted);
// CP_WAIT(1) at top ensures W(ck), X(ck) ready while X(ck+1) stays in flight.
// q (scaled by log2e), k, v all written as bf16.
// ---------------------------------------------------------------------------
#define PW_STR 36
#define PX_STR 136
#define PW_BYTES (64 * PW_STR * 4)        // 9216
#define PX_BYTES (32 * PX_STR * 4)        // 17408
#define PSW_OFF  0
#define PSX_OFF  (2 * PW_BYTES)           // 18432
#define SMEM_PROJ (PSX_OFF + 3 * PX_BYTES) // 70656

__global__ __launch_bounds__(256, 3) void proj_kernel(
    const float* __restrict__ x,
    const float* __restrict__ Wq, const float* __restrict__ bq,
    const float* __restrict__ Wk, const float* __restrict__ bk,
    const float* __restrict__ Wv, const float* __restrict__ bv)
{
    extern __shared__ char smem[];
    const uint32_t sb = smem_u32(smem);
    float* sW = (float*)(smem + PSW_OFF);
    float* sX = (float*)(smem + PSX_OFF);

    const int b  = blockIdx.z;
    const int r0 = blockIdx.y * 64;
    const int l0 = blockIdx.x * 128;
    const int tid  = threadIdx.x;
    const int lane = tid & 31;
    const int w    = tid >> 5;
    const int g    = lane >> 2;
    const int t4   = lane & 3;
    const int mb   = (w & 3) * 16;
    const int lw   = (w >> 2) * 64;

    const float* xb = x + (size_t)b * C_ * L_;

    auto wrow = [&](int r) -> const float* {
        if (r < D_)          return Wq + (size_t)r * C_;
        else if (r < 2 * D_) return Wk + (size_t)(r - D_) * C_;
        else                 return Wv + (size_t)(r - 2 * D_) * C_;
    };
    auto load_w = [&](int ck) {                   // W chunk ck -> wbuf ck&1
        #pragma unroll
        for (int t = 0; t < 2; t++) {
            int idx = tid + t * 256;              // 512 = 64 rows x 8 segs
            int row = idx >> 3, seg = idx & 7;
            CP16(sb + PSW_OFF + (ck & 1) * PW_BYTES + row * (PW_STR * 4) + seg * 16,
                 wrow(r0 + row) + ck * 32 + seg * 4);
        }
    };
    auto load_x = [&](int ck) {                   // X chunk ck -> xbuf ck%3
        const int st = ck % 3;
        #pragma unroll
        for (int t = 0; t < 4; t++) {
            int idx = tid + t * 256;              // 1024 = 32 rows x 32 segs
            int row = idx >> 5, seg = idx & 31;
            CP16(sb + PSX_OFF + st * PX_BYTES + row * (PX_STR * 4) + seg * 16,
                 xb + (size_t)(ck * 32 + row) * L_ + l0 + seg * 4);
        }
    };

    // prologue: group A = {W0, X0}; group B = {X1}
    load_w(0);
    load_x(0);
    CP_COMMIT();
    load_x(1);
    CP_COMMIT();

    const int r_g  = r0 + mb + g;
    const int r_g8 = r_g + 8;
    float bias_lo, bias_hi;
    {
        auto bsel = [&](int r) -> float {
            if (r < D_)          return bq[r];
            else if (r < 2 * D_) return bk[r - D_];
            else                 return bv[r - 2 * D_];
        };
        bias_lo = bsel(r_g);
        bias_hi = bsel(r_g8);
    }
    float o[8][4];
    #pragma unroll
    for (int nt = 0; nt < 8; nt++) {
        o[nt][0] = bias_lo; o[nt][1] = bias_lo;
        o[nt][2] = bias_hi; o[nt][3] = bias_hi;
    }

    for (int ck = 0; ck < 8; ck++) {
        CP_WAIT(1);                    // newest group (X ck+1) may stay in flight
        __syncthreads();
        if (ck < 7) {
            load_w(ck + 1);
            CP_COMMIT();               // group {W(ck+1)}
            if (ck < 6) load_x(ck + 2);
            CP_COMMIT();               // group {X(ck+2)} (empty when ck==6)
        }
        const float* sWb = sW + (ck & 1) * (64 * PW_STR);
        const float* sXb = sX + (ck % 3) * (32 * PX_STR);
        #pragma unroll
        for (int s = 0; s < 4; s++) {
            uint32_t a0 = __float_as_uint(sWb[(mb + g) * PW_STR + s * 8 + t4]);
            uint32_t a1 = __float_as_uint(sWb[(mb + g + 8) * PW_STR + s * 8 + t4]);
            uint32_t a2 = __float_as_uint(sWb[(mb + g) * PW_STR + s * 8 + t4 + 4]);
            uint32_t a3 = __float_as_uint(sWb[(mb + g + 8) * PW_STR + s * 8 + t4 + 4]);
            #pragma unroll
            for (int nt = 0; nt < 8; nt++) {
                const int n = lw + nt * 8 + g;
                uint32_t b0 = __float_as_uint(sXb[(s * 8 + t4) * PX_STR + n]);
                uint32_t b1 = __float_as_uint(sXb[(s * 8 + t4 + 4) * PX_STR + n]);
                MMA_TF32(o[nt][0], o[nt][1], o[nt][2], o[nt][3],
                         a0, a1, a2, a3, b0, b1);
            }
        }
    }

    if (r_g < 2 * D_) {
        const bool isq = (r_g < D_);
        __nv_bfloat16* dst = isq ? (g_q + (size_t)b * L_ * D_)
                                 : (g_k + (size_t)b * L_ * D_);
        const float sc = isq ? LOG2E : 1.0f;
        const int d  = isq ? r_g : (r_g - D_);
        const int d8 = d + 8;
        #pragma unroll
        for (int nt = 0; nt < 8; nt++) {
            const int l = l0 + lw + nt * 8 + t4 * 2;
            dst[(size_t)l * D_ + d]        = __float2bfloat16_rn(o[nt][0] * sc);
            dst[(size_t)(l + 1) * D_ + d]  = __float2bfloat16_rn(o[nt][1] * sc);
            dst[(size_t)l * D_ + d8]       = __float2bfloat16_rn(o[nt][2] * sc);
            dst[(size_t)(l + 1) * D_ + d8] = __float2bfloat16_rn(o[nt][3] * sc);
        }
    } else {
        __nv_bfloat16* vb = g_v + (size_t)b * C_ * L_;
        const int c = r_g - 2 * D_, c8 = c + 8;
        #pragma unroll
        for (int nt = 0; nt < 8; nt++) {
            const int l = l0 + lw + nt * 8 + t4 * 2;
            uint32_t lo, hi;
            CVT_BF16X2_F32(lo, o[nt][0], o[nt][1]);
            CVT_BF16X2_F32(hi, o[nt][2], o[nt][3]);
            *(uint32_t*)&vb[(size_t)c * L_ + l]  = lo;
            *(uint32_t*)&vb[(size_t)c8 * L_ + l] = hi;
        }
    }
}

// ---------------------------------------------------------------------------
// Kernel 2: bf16 mma.sync flash attention [round-13 attn, 88.2 µs measured].
// 64 q x 256 c blocks, 256 threads = 8 warps (2 m-groups x 4 c-quarters),
// S dedup + per-m-group named barrier between stage A and stage B.
// SMEM: sQ [64][80B] | sK 2x[64][80B] | sV 2x[256][144B] | sP 2x[32][144B] | sRS
// ---------------------------------------------------------------------------
#define QKROW 80
#define VROW  144
#define SQ_OFF  0
#define SK_OFF  5120
#define SKB     5120
#define SV_OFF  15360
#define SVB     36864
#define SP_OFF  89088
#define SPM     4608                   // 32 rows x 144 B per m-group
#define SRS_OFF 98304                  // 64 rows x 4 cq floats = 1024 B
#define SMEM_AT 99328

__global__ __launch_bounds__(256, 2) void attn_kernel(
    const float* __restrict__ x, const float* __restrict__ gamma_p,
    float* __restrict__ out)
{
    extern __shared__ char smem[];
    const uint32_t sb = smem_u32(smem);

    const int tid  = threadIdx.x;
    const int lane = tid & 31;
    const int w    = tid >> 5;
    const int g    = lane >> 2;
    const int t4   = lane & 3;
    const int mgrp = w >> 2;           // 0/1 : q rows mgrp*32..+31 (warps 0-3 / 4-7)
    const int cq   = w & 3;            // 0..3 : c cols cq*64..+63
    const int lr   = lane & 7;
    const int l8   = (lane >> 3) & 1;
    const int l16  = (lane >> 4) & 1;

    const int b  = blockIdx.y;
    const int m0 = blockIdx.x * 64;

    const __nv_bfloat16* qg = g_q + (size_t)b * L_ * D_;
    const __nv_bfloat16* kg = g_k + (size_t)b * L_ * D_;
    const __nv_bfloat16* vg = g_v + (size_t)b * C_ * L_;

    // ---- ldmatrix / STS base addresses ----
    const uint32_t qlm  = sb + SQ_OFF + (uint32_t)(mgrp * 32 + lr + l8 * 8) * QKROW + l16 * 16;
    const uint32_t klmb = sb + SK_OFF + (uint32_t)(16 * cq + lr) * QKROW + (lane >> 3) * 16;
    const uint32_t vlmb = sb + SV_OFF + (uint32_t)(cq * 64 + l16 * 8 + lr) * VROW + l8 * 16;
    const uint32_t plm  = sb + SP_OFF + mgrp * SPM + (uint32_t)(lr + l8 * 8) * VROW + l16 * 16;
    const uint32_t psta = sb + SP_OFF + mgrp * SPM + (uint32_t)g * VROW + (16 * cq + 2 * t4) * 2;

    // ---- preload Q (64x32), K0, V0 ----
    {
        int row = tid >> 2, seg = tid & 3;
        CP16(sb + SQ_OFF + row * QKROW + seg * 16, qg + (size_t)(m0 + row) * D_ + seg * 8);
        CP16(sb + SK_OFF + row * QKROW + seg * 16, kg + (size_t)row * D_ + seg * 8);
        #pragma unroll
        for (int t = 0; t < 8; t++) {
            int idx = tid + t * 256;
            int r = idx >> 3, s = idx & 7;
            CP16(sb + SV_OFF + r * VROW + s * 16, vg + (size_t)r * L_ + s * 8);
        }
        CP_COMMIT();
    }

    uint32_t qa[2][8];                 // 2 m-tiles x (k0-15: 4, k16-31: 4)
    float o[16][4];                    // [i*8 + ct2][4]
    #pragma unroll
    for (int i = 0; i < 16; i++)
        #pragma unroll
        for (int j = 0; j < 4; j++) o[i][j] = 0.f;
    float rs[4] = {0.f, 0.f, 0.f, 0.f};   // rows: i0 g, i0 g+8, i1 g, i1 g+8

    for (int it = 0; it < 32; it++) {
        const int buf = it & 1;
        CP_WAIT(0);
        __syncthreads();

        if (it == 0) {
            #pragma unroll
            for (int i = 0; i < 2; i++) {
                LDMATRIX_X4(qa[i][0], qa[i][1], qa[i][2], qa[i][3],
                            qlm + i * (16 * QKROW));
                LDMATRIX_X4(qa[i][4], qa[i][5], qa[i][6], qa[i][7],
                            qlm + i * (16 * QKROW) + 32);
            }
        }

        if (it < 31) {
            const int n1 = (it + 1) * 64;
            const int pb = (it + 1) & 1;
            int row = tid >> 2, seg = tid & 3;
            CP16(sb + SK_OFF + pb * SKB + row * QKROW + seg * 16,
                 kg + (size_t)(n1 + row) * D_ + seg * 8);
            #pragma unroll
            for (int t = 0; t < 8; t++) {
                int idx = tid + t * 256;
                int r = idx >> 3, s = idx & 7;
                CP16(sb + SV_OFF + pb * SVB + r * VROW + s * 16,
                     vg + (size_t)r * L_ + n1 + s * 8);
            }
            CP_COMMIT();
        }

        const uint32_t klm = klmb + buf * SKB;
        const uint32_t vlm = vlmb + buf * SVB;

        // ---- stage A: S(32q x 16 keys of quarter cq), ex2, pack -> sP ----
        #pragma unroll
        for (int t = 0; t < 2; t++) {
            uint32_t kb0, kb1, kb2, kb3;
            LDMATRIX_X4(kb0, kb1, kb2, kb3, klm + t * (8 * QKROW));
            #pragma unroll
            for (int i = 0; i < 2; i++) {
                float d0 = 0.f, d1 = 0.f, d2 = 0.f, d3 = 0.f;
                MMA_BF16(d0, d1, d2, d3,
                         qa[i][0], qa[i][1], qa[i][2], qa[i][3], kb0, kb1);
                MMA_BF16(d0, d1, d2, d3,
                         qa[i][4], qa[i][5], qa[i][6], qa[i][7], kb2, kb3);
                float e0, e1, e2, e3;
                EX2F(e0, d0); EX2F(e1, d1); EX2F(e2, d2); EX2F(e3, d3);
                rs[2 * i]     += e0 + e1;
                rs[2 * i + 1] += e2 + e3;
                uint32_t lo, hi;
                CVT_BF16X2_F32(lo, e0, e1);
                CVT_BF16X2_F32(hi, e2, e3);
                STS32(psta + i * (16 * VROW) + t * 16, lo);
                STS32(psta + i * (16 * VROW) + 8 * VROW + t * 16, hi);
            }
        }
        // per-m-group sync: P producers == P consumers == warps of this mgrp
        NAMED_BAR(1 + mgrp, 128);

        // ---- stage B: O += P Vt (P frags from sP, V frags shared by 2 m-tiles) ----
        #pragma unroll
        for (int j = 0; j < 4; j++) {
            uint32_t a0[4], a1[4];
            LDMATRIX_X4(a0[0], a0[1], a0[2], a0[3], plm + j * 32);
            LDMATRIX_X4(a1[0], a1[1], a1[2], a1[3], plm + 16 * VROW + j * 32);
            #pragma unroll
            for (int cp = 0; cp < 4; cp++) {
                uint32_t v0, v1, v2, v3;
                LDMATRIX_X4(v0, v1, v2, v3, vlm + cp * (16 * VROW) + j * 32);
                MMA_BF16(o[2*cp][0], o[2*cp][1], o[2*cp][2], o[2*cp][3],
                         a0[0], a0[1], a0[2], a0[3], v0, v1);
                MMA_BF16(o[2*cp+1][0], o[2*cp+1][1], o[2*cp+1][2], o[2*cp+1][3],
                         a0[0], a0[1], a0[2], a0[3], v2, v3);
                MMA_BF16(o[8+2*cp][0], o[8+2*cp][1], o[8+2*cp][2], o[8+2*cp][3],
                         a1[0], a1[1], a1[2], a1[3], v0, v1);
                MMA_BF16(o[8+2*cp+1][0], o[8+2*cp+1][1], o[8+2*cp+1][2], o[8+2*cp+1][3],
                         a1[0], a1[1], a1[2], a1[3], v2, v3);
            }
        }
    }

    // ---- rowsums: t4 shfl reduce, then combine 4 c-quarters via smem ----
    #pragma unroll
    for (int r = 0; r < 4; r++) {
        rs[r] += __shfl_xor_sync(0xFFFFFFFFu, rs[r], 1);
        rs[r] += __shfl_xor_sync(0xFFFFFFFFu, rs[r], 2);
    }
    float* sRS = (float*)(smem + SRS_OFF);
    if (t4 == 0) {
        sRS[(mgrp * 32 + g) * 4 + cq]           = rs[0];
        sRS[(mgrp * 32 + g + 8) * 4 + cq]       = rs[1];
        sRS[(mgrp * 32 + 16 + g) * 4 + cq]      = rs[2];
        sRS[(mgrp * 32 + 16 + g + 8) * 4 + cq]  = rs[3];
    }
    __syncthreads();

    const float gam = gamma_p[0];
    float inv[4];
    #pragma unroll
    for (int r = 0; r < 4; r++) {
        const int row = mgrp * 32 + 16 * (r >> 1) + (r & 1) * 8 + g;
        inv[r] = gam / (sRS[row * 4] + sRS[row * 4 + 1] + sRS[row * 4 + 2] + sRS[row * 4 + 3]);
    }

    const float* xb = x + (size_t)b * C_ * L_;
    float* ob = out + (size_t)b * C_ * L_;
    #pragma unroll
    for (int i = 0; i < 2; i++) {
        const int mA = m0 + mgrp * 32 + 16 * i + g;
        const int mB = mA + 8;
        const float iA = inv[2 * i], iB = inv[2 * i + 1];
        #pragma unroll
        for (int ct = 0; ct < 8; ct++) {
            const int c0 = cq * 64 + ct * 8 + t4 * 2;
            const int oi = i * 8 + ct;
            ob[(size_t)c0 * L_ + mA]       = o[oi][0] * iA + xb[(size_t)c0 * L_ + mA];
            ob[(size_t)(c0 + 1) * L_ + mA] = o[oi][1] * iA + xb[(size_t)(c0 + 1) * L_ + mA];
            ob[(size_t)c0 * L_ + mB]       = o[oi][2] * iB + xb[(size_t)c0 * L_ + mB];
            ob[(size_t)(c0 + 1) * L_ + mB] = o[oi][3] * iB + xb[(size_t)(c0 + 1) * L_ + mB];
        }
    }
}

// ---------------------------------------------------------------------------
extern "C" void kernel_launch(void* const* d_in, const int* in_sizes, int n_in,
                              void* d_out, int out_size)
{
    (void)in_sizes; (void)n_in; (void)out_size;
    const float* x     = (const float*)d_in[0];
    const float* Wq    = (const float*)d_in[1];
    const float* bq    = (const float*)d_in[2];
    const float* Wk    = (const float*)d_in[3];
    const float* bk    = (const float*)d_in[4];
    const float* Wv    = (const float*)d_in[5];
    const float* bv    = (const float*)d_in[6];
    const float* gamma = (const float*)d_in[7];
    float* out = (float*)d_out;

    cudaFuncSetAttribute(proj_kernel, cudaFuncAttributeMaxDynamicSharedMemorySize, SMEM_PROJ);
    proj_kernel<<<dim3(L_ / 128, 5, B_), 256, SMEM_PROJ>>>(x, Wq, bq, Wk, bk, Wv, bv);

    cudaFuncSetAttribute(attn_kernel, cudaFuncAttributeMaxDynamicSharedMemorySize, SMEM_AT);
    attn_kernel<<<dim3(L_ / 64, B_), 256, SMEM_AT>>>(x, gamma, out);
}

// round 15
// speedup vs baseline: 1.4155x; 1.0649x over previous
#include <cuda_runtime.h>
#include <cuda_bf16.h>
#include <cstdint>

#define B_ 8
#define C_ 256
#define L_ 2048
#define D_ 32
#define LOG2E 1.4426950408889634f

// scratch: bf16 inputs + projections (q pre-scaled by log2(e))
__device__ __nv_bfloat16 g_wb[320 * 256];             // [r][c] bf16 (Wq*log2e | Wk | Wv)
__device__ float         g_bias[320];                 // bq*log2e | bk | bv
__device__ __nv_bfloat16 g_xb[(size_t)B_ * C_ * L_];  // [b][c][l] bf16
__device__ __nv_bfloat16 g_q[(size_t)B_ * L_ * D_];   // [b][l][32] bf16
__device__ __nv_bfloat16 g_k[(size_t)B_ * L_ * D_];   // [b][l][32] bf16
__device__ __nv_bfloat16 g_v[(size_t)B_ * C_ * L_];   // [b][c][l]  bf16

// ---------------------------------------------------------------------------
// helpers
// ---------------------------------------------------------------------------
__device__ __forceinline__ uint32_t smem_u32(const void* p) {
    uint32_t a;
    asm("{ .reg .u64 t; cvta.to.shared.u64 t, %1; cvt.u32.u64 %0, t; }" : "=r"(a) : "l"(p));
    return a;
}
#define CP16(dst, src) \
    asm volatile("cp.async.cg.shared.global [%0], [%1], 16;" :: "r"(dst), "l"(src))
#define CP_COMMIT() asm volatile("cp.async.commit_group;")
#define CP_WAIT(n)  asm volatile("cp.async.wait_group %0;" :: "n"(n))

#define CVT_BF16X2_F32(result, a, b) \
    asm("cvt.rn.satfinite.bf16x2.f32 %0, %1, %2;" : "=r"(result) : "f"(b), "f"(a))

#define EX2F(d, s) asm("ex2.approx.f32 %0, %1;" : "=f"(d) : "f"(s))

#define STS32(addr, val) \
    asm volatile("st.shared.b32 [%0], %1;" :: "r"(addr), "r"(val) : "memory")

#define NAMED_BAR(id, cnt) \
    asm volatile("bar.sync %0, %1;" :: "r"(id), "r"(cnt) : "memory")

#define LDMATRIX_X4(r0, r1, r2, r3, addr) \
    asm volatile("ldmatrix.sync.aligned.m8n8.x4.shared.b16 {%0,%1,%2,%3}, [%4];" \
        : "=r"(r0), "=r"(r1), "=r"(r2), "=r"(r3) : "r"(addr))

#define LDMATRIX_X4_T(r0, r1, r2, r3, addr) \
    asm volatile("ldmatrix.sync.aligned.m8n8.x4.trans.shared.b16 {%0,%1,%2,%3}, [%4];" \
        : "=r"(r0), "=r"(r1), "=r"(r2), "=r"(r3) : "r"(addr))

#define MMA_BF16(d0,d1,d2,d3,a0,a1,a2,a3,b0,b1) \
    asm volatile("mma.sync.aligned.m16n8k16.row.col.f32.bf16.bf16.f32 " \
        "{%0,%1,%2,%3}, {%4,%5,%6,%7}, {%8,%9}, {%0,%1,%2,%3};" \
        : "+f"(d0), "+f"(d1), "+f"(d2), "+f"(d3) \
        : "r"(a0), "r"(a1), "r"(a2), "r"(a3), "r"(b0), "r"(b1))

// ---------------------------------------------------------------------------
// Kernel 0a: convert W (+fold log2e into Wq/bq) to bf16. grid 320 x 256 thr.
// ---------------------------------------------------------------------------
__global__ void conv_w_kernel(
    const float* __restrict__ Wq, const float* __restrict__ bq,
    const float* __restrict__ Wk, const float* __restrict__ bk,
    const float* __restrict__ Wv, const float* __restrict__ bv)
{
    const int r = blockIdx.x;
    const int tid = threadIdx.x;
    const float* src;
    float bias, sc;
    if (r < D_)          { src = Wq + (size_t)r * C_;            bias = bq[r];          sc = LOG2E; }
    else if (r < 2 * D_) { src = Wk + (size_t)(r - D_) * C_;     bias = bk[r - D_];     sc = 1.f;  }
    else                 { src = Wv + (size_t)(r - 2 * D_) * C_; bias = bv[r - 2 * D_]; sc = 1.f;  }
    g_wb[(size_t)r * C_ + tid] = __float2bfloat16_rn(src[tid] * sc);
    if (tid == 0) g_bias[r] = bias * sc;
}

// ---------------------------------------------------------------------------
// Kernel 0b: convert x to bf16 (same layout). grid 2048 x 256 thr, 8 elems/thr.
// ---------------------------------------------------------------------------
__global__ __launch_bounds__(256) void conv_x_kernel(const float* __restrict__ x)
{
    const size_t base = (size_t)blockIdx.x * 2048 + threadIdx.x * 8;
    float4 a = *(const float4*)(x + base);
    float4 b = *(const float4*)(x + base + 4);
    uint4 o;
    CVT_BF16X2_F32(o.x, a.x, a.y);
    CVT_BF16X2_F32(o.y, a.z, a.w);
    CVT_BF16X2_F32(o.z, b.x, b.y);
    CVT_BF16X2_F32(o.w, b.z, b.w);
    *(uint4*)(g_xb + base) = o;
}

// ---------------------------------------------------------------------------
// Kernel 1: QKV projection via bf16 mma.sync, ldmatrix fragments.
//   A = W bf16 [r][c] (k-major, normal ldmatrix);
//   B = x bf16 [c][l] (k-row-major, ldmatrix.trans).
// Block: 64 r x 128 l, 256 threads = 8 warps (4 m-tiles x 2 l-halves of 64).
// k=256 in 8 chunks of 32, double-buffered. Grid (16, 5, 8), 3 blocks/SM.
// SMEM: sW 2x[64][80B] | sX 2x[32][272B]  (27.6 KB)
// ---------------------------------------------------------------------------
#define WROW 80
#define XROW 272
#define PJW_OFF 0
#define PJW_B   (64 * WROW)               // 5120
#define PJX_OFF (2 * PJW_B)               // 10240
#define PJX_B   (32 * XROW)               // 8704
#define SMEM_PROJ (PJX_OFF + 2 * PJX_B)   // 27648

__global__ __launch_bounds__(256, 3) void proj_kernel()
{
    extern __shared__ char smem[];
    const uint32_t sb = smem_u32(smem);

    const int b  = blockIdx.z;
    const int r0 = blockIdx.y * 64;
    const int l0 = blockIdx.x * 128;
    const int tid  = threadIdx.x;
    const int lane = tid & 31;
    const int w    = tid >> 5;
    const int g    = lane >> 2;
    const int t4   = lane & 3;
    const int mb   = (w & 3) * 16;
    const int lw   = (w >> 2) * 64;
    const int lr   = lane & 7;
    const int l8   = (lane >> 3) & 1;
    const int l16  = (lane >> 4) & 1;

    const __nv_bfloat16* xg = g_xb + (size_t)b * C_ * L_;

    auto load_w = [&](int ck) {            // W chunk ck (32 c) -> wbuf ck&1
        int row = tid >> 2, seg = tid & 3; // 64 rows x 4 segs of 16B
        CP16(sb + PJW_OFF + (ck & 1) * PJW_B + row * WROW + seg * 16,
             g_wb + (size_t)(r0 + row) * C_ + ck * 32 + seg * 8);
    };
    auto load_x = [&](int ck) {            // X chunk ck (32 c x 128 l) -> xbuf ck&1
        #pragma unroll
        for (int t = 0; t < 2; t++) {
            int idx = tid + t * 256;       // 512 = 32 rows x 16 segs of 16B
            int row = idx >> 4, seg = idx & 15;
            CP16(sb + PJX_OFF + (ck & 1) * PJX_B + row * XROW + seg * 16,
                 xg + (size_t)(ck * 32 + row) * L_ + l0 + seg * 8);
        }
    };

    load_w(0);
    load_x(0);
    CP_COMMIT();

    // ldmatrix base addresses
    const uint32_t wlm = sb + PJW_OFF + (uint32_t)(mb + lr + l8 * 8) * WROW + l16 * 16;
    // B (trans): lane groups -> (k rows lr + l8*8, n-block l16*8)
    const uint32_t xlm = sb + PJX_OFF + (uint32_t)(lr + l8 * 8) * XROW
                       + (uint32_t)(lw + l16 * 8) * 2;

    const int r_g  = r0 + mb + g;
    const int r_g8 = r_g + 8;
    const float bias_lo = g_bias[r_g];
    const float bias_hi = g_bias[r_g8];
    float o[8][4];
    #pragma unroll
    for (int nt = 0; nt < 8; nt++) {
        o[nt][0] = bias_lo; o[nt][1] = bias_lo;
        o[nt][2] = bias_hi; o[nt][3] = bias_hi;
    }

    for (int ck = 0; ck < 8; ck++) {
        const int buf = ck & 1;
        CP_WAIT(0);
        __syncthreads();
        if (ck < 7) {
            load_w(ck + 1);
            load_x(ck + 1);
            CP_COMMIT();
        }
        const uint32_t wb = wlm + buf * PJW_B;
        const uint32_t xbm = xlm + buf * PJX_B;
        #pragma unroll
        for (int s01 = 0; s01 < 2; s01++) {
            uint32_t a0, a1, a2, a3;
            LDMATRIX_X4(a0, a1, a2, a3, wb + s01 * 32);
            #pragma unroll
            for (int np = 0; np < 4; np++) {
                uint32_t b0, b1, b2, b3;
                LDMATRIX_X4_T(b0, b1, b2, b3,
                              xbm + s01 * (16 * XROW) + np * 32);
                MMA_BF16(o[2*np][0], o[2*np][1], o[2*np][2], o[2*np][3],
                         a0, a1, a2, a3, b0, b1);
                MMA_BF16(o[2*np+1][0], o[2*np+1][1], o[2*np+1][2], o[2*np+1][3],
                         a0, a1, a2, a3, b2, b3);
            }
        }
    }

    if (r_g < 2 * D_) {
        const bool isq = (r_g < D_);
        __nv_bfloat16* dst = isq ? (g_q + (size_t)b * L_ * D_)
                                 : (g_k + (size_t)b * L_ * D_);
        const int d  = isq ? r_g : (r_g - D_);
        const int d8 = d + 8;
        #pragma unroll
        for (int nt = 0; nt < 8; nt++) {
            const int l = l0 + lw + nt * 8 + t4 * 2;
            dst[(size_t)l * D_ + d]        = __float2bfloat16_rn(o[nt][0]);
            dst[(size_t)(l + 1) * D_ + d]  = __float2bfloat16_rn(o[nt][1]);
            dst[(size_t)l * D_ + d8]       = __float2bfloat16_rn(o[nt][2]);
            dst[(size_t)(l + 1) * D_ + d8] = __float2bfloat16_rn(o[nt][3]);
        }
    } else {
        __nv_bfloat16* vb = g_v + (size_t)b * C_ * L_;
        const int c = r_g - 2 * D_, c8 = c + 8;
        #pragma unroll
        for (int nt = 0; nt < 8; nt++) {
            const int l = l0 + lw + nt * 8 + t4 * 2;
            uint32_t lo, hi;
            CVT_BF16X2_F32(lo, o[nt][0], o[nt][1]);
            CVT_BF16X2_F32(hi, o[nt][2], o[nt][3]);
            *(uint32_t*)&vb[(size_t)c * L_ + l]  = lo;
            *(uint32_t*)&vb[(size_t)c8 * L_ + l] = hi;
        }
    }
}

// ---------------------------------------------------------------------------
// Kernel 2: bf16 mma.sync flash attention [round-13 attn, 88.2 µs measured].
// 64 q x 256 c blocks, 256 threads = 8 warps (2 m-groups x 4 c-quarters),
// S dedup + per-m-group named barrier between stage A and stage B.
// SMEM: sQ [64][80B] | sK 2x[64][80B] | sV 2x[256][144B] | sP 2x[32][144B] | sRS
// ---------------------------------------------------------------------------
#define QKROW 80
#define VROW  144
#define SQ_OFF  0
#define SK_OFF  5120
#define SKB     5120
#define SV_OFF  15360
#define SVB     36864
#define SP_OFF  89088
#define SPM     4608                   // 32 rows x 144 B per m-group
#define SRS_OFF 98304                  // 64 rows x 4 cq floats = 1024 B
#define SMEM_AT 99328

__global__ __launch_bounds__(256, 2) void attn_kernel(
    const float* __restrict__ x, const float* __restrict__ gamma_p,
    float* __restrict__ out)
{
    extern __shared__ char smem[];
    const uint32_t sb = smem_u32(smem);

    const int tid  = threadIdx.x;
    const int lane = tid & 31;
    const int w    = tid >> 5;
    const int g    = lane >> 2;
    const int t4   = lane & 3;
    const int mgrp = w >> 2;           // 0/1 : q rows mgrp*32..+31 (warps 0-3 / 4-7)
    const int cq   = w & 3;            // 0..3 : c cols cq*64..+63
    const int lr   = lane & 7;
    const int l8   = (lane >> 3) & 1;
    const int l16  = (lane >> 4) & 1;

    const int b  = blockIdx.y;
    const int m0 = blockIdx.x * 64;

    const __nv_bfloat16* qg = g_q + (size_t)b * L_ * D_;
    const __nv_bfloat16* kg = g_k + (size_t)b * L_ * D_;
    const __nv_bfloat16* vg = g_v + (size_t)b * C_ * L_;

    // ---- ldmatrix / STS base addresses ----
    const uint32_t qlm  = sb + SQ_OFF + (uint32_t)(mgrp * 32 + lr + l8 * 8) * QKROW + l16 * 16;
    const uint32_t klmb = sb + SK_OFF + (uint32_t)(16 * cq + lr) * QKROW + (lane >> 3) * 16;
    const uint32_t vlmb = sb + SV_OFF + (uint32_t)(cq * 64 + l16 * 8 + lr) * VROW + l8 * 16;
    const uint32_t plm  = sb + SP_OFF + mgrp * SPM + (uint32_t)(lr + l8 * 8) * VROW + l16 * 16;
    const uint32_t psta = sb + SP_OFF + mgrp * SPM + (uint32_t)g * VROW + (16 * cq + 2 * t4) * 2;

    // ---- preload Q (64x32), K0, V0 ----
    {
        int row = tid >> 2, seg = tid & 3;
        CP16(sb + SQ_OFF + row * QKROW + seg * 16, qg + (size_t)(m0 + row) * D_ + seg * 8);
        CP16(sb + SK_OFF + row * QKROW + seg * 16, kg + (size_t)row * D_ + seg * 8);
        #pragma unroll
        for (int t = 0; t < 8; t++) {
            int idx = tid + t * 256;
            int r = idx >> 3, s = idx & 7;
            CP16(sb + SV_OFF + r * VROW + s * 16, vg + (size_t)r * L_ + s * 8);
        }
        CP_COMMIT();
    }

    uint32_t qa[2][8];                 // 2 m-tiles x (k0-15: 4, k16-31: 4)
    float o[16][4];                    // [i*8 + ct2][4]
    #pragma unroll
    for (int i = 0; i < 16; i++)
        #pragma unroll
        for (int j = 0; j < 4; j++) o[i][j] = 0.f;
    float rs[4] = {0.f, 0.f, 0.f, 0.f};   // rows: i0 g, i0 g+8, i1 g, i1 g+8

    for (int it = 0; it < 32; it++) {
        const int buf = it & 1;
        CP_WAIT(0);
        __syncthreads();

        if (it == 0) {
            #pragma unroll
            for (int i = 0; i < 2; i++) {
                LDMATRIX_X4(qa[i][0], qa[i][1], qa[i][2], qa[i][3],
                            qlm + i * (16 * QKROW));
                LDMATRIX_X4(qa[i][4], qa[i][5], qa[i][6], qa[i][7],
                            qlm + i * (16 * QKROW) + 32);
            }
        }

        if (it < 31) {
            const int n1 = (it + 1) * 64;
            const int pb = (it + 1) & 1;
            int row = tid >> 2, seg = tid & 3;
            CP16(sb + SK_OFF + pb * SKB + row * QKROW + seg * 16,
                 kg + (size_t)(n1 + row) * D_ + seg * 8);
            #pragma unroll
            for (int t = 0; t < 8; t++) {
                int idx = tid + t * 256;
                int r = idx >> 3, s = idx & 7;
                CP16(sb + SV_OFF + pb * SVB + r * VROW + s * 16,
                     vg + (size_t)r * L_ + n1 + s * 8);
            }
            CP_COMMIT();
        }

        const uint32_t klm = klmb + buf * SKB;
        const uint32_t vlm = vlmb + buf * SVB;

        // ---- stage A: S(32q x 16 keys of quarter cq), ex2, pack -> sP ----
        #pragma unroll
        for (int t = 0; t < 2; t++) {
            uint32_t kb0, kb1, kb2, kb3;
            LDMATRIX_X4(kb0, kb1, kb2, kb3, klm + t * (8 * QKROW));
            #pragma unroll
            for (int i = 0; i < 2; i++) {
                float d0 = 0.f, d1 = 0.f, d2 = 0.f, d3 = 0.f;
                MMA_BF16(d0, d1, d2, d3,
                         qa[i][0], qa[i][1], qa[i][2], qa[i][3], kb0, kb1);
                MMA_BF16(d0, d1, d2, d3,
                         qa[i][4], qa[i][5], qa[i][6], qa[i][7], kb2, kb3);
                float e0, e1, e2, e3;
                EX2F(e0, d0); EX2F(e1, d1); EX2F(e2, d2); EX2F(e3, d3);
                rs[2 * i]     += e0 + e1;
                rs[2 * i + 1] += e2 + e3;
                uint32_t lo, hi;
                CVT_BF16X2_F32(lo, e0, e1);
                CVT_BF16X2_F32(hi, e2, e3);
                STS32(psta + i * (16 * VROW) + t * 16, lo);
                STS32(psta + i * (16 * VROW) + 8 * VROW + t * 16, hi);
            }
        }
        // per-m-group sync: P producers == P consumers == warps of this mgrp
        NAMED_BAR(1 + mgrp, 128);

        // ---- stage B: O += P Vt (P frags from sP, V frags shared by 2 m-tiles) ----
        #pragma unroll
        for (int j = 0; j < 4; j++) {
            uint32_t a0[4], a1[4];
            LDMATRIX_X4(a0[0], a0[1], a0[2], a0[3], plm + j * 32);
            LDMATRIX_X4(a1[0], a1[1], a1[2], a1[3], plm + 16 * VROW + j * 32);
            #pragma unroll
            for (int cp = 0; cp < 4; cp++) {
                uint32_t v0, v1, v2, v3;
                LDMATRIX_X4(v0, v1, v2, v3, vlm + cp * (16 * VROW) + j * 32);
                MMA_BF16(o[2*cp][0], o[2*cp][1], o[2*cp][2], o[2*cp][3],
                         a0[0], a0[1], a0[2], a0[3], v0, v1);
                MMA_BF16(o[2*cp+1][0], o[2*cp+1][1], o[2*cp+1][2], o[2*cp+1][3],
                         a0[0], a0[1], a0[2], a0[3], v2, v3);
                MMA_BF16(o[8+2*cp][0], o[8+2*cp][1], o[8+2*cp][2], o[8+2*cp][3],
                         a1[0], a1[1], a1[2], a1[3], v0, v1);
                MMA_BF16(o[8+2*cp+1][0], o[8+2*cp+1][1], o[8+2*cp+1][2], o[8+2*cp+1][3],
                         a1[0], a1[1], a1[2], a1[3], v2, v3);
            }
        }
    }

    // ---- rowsums: t4 shfl reduce, then combine 4 c-quarters via smem ----
    #pragma unroll
    for (int r = 0; r < 4; r++) {
        rs[r] += __shfl_xor_sync(0xFFFFFFFFu, rs[r], 1);
        rs[r] += __shfl_xor_sync(0xFFFFFFFFu, rs[r], 2);
    }
    float* sRS = (float*)(smem + SRS_OFF);
    if (t4 == 0) {
        sRS[(mgrp * 32 + g) * 4 + cq]           = rs[0];
        sRS[(mgrp * 32 + g + 8) * 4 + cq]       = rs[1];
        sRS[(mgrp * 32 + 16 + g) * 4 + cq]      = rs[2];
        sRS[(mgrp * 32 + 16 + g + 8) * 4 + cq]  = rs[3];
    }
    __syncthreads();

    const float gam = gamma_p[0];
    float inv[4];
    #pragma unroll
    for (int r = 0; r < 4; r++) {
        const int row = mgrp * 32 + 16 * (r >> 1) + (r & 1) * 8 + g;
        inv[r] = gam / (sRS[row * 4] + sRS[row * 4 + 1] + sRS[row * 4 + 2] + sRS[row * 4 + 3]);
    }

    const float* xb = x + (size_t)b * C_ * L_;
    float* ob = out + (size_t)b * C_ * L_;
    #pragma unroll
    for (int i = 0; i < 2; i++) {
        const int mA = m0 + mgrp * 32 + 16 * i + g;
        const int mB = mA + 8;
        const float iA = inv[2 * i], iB = inv[2 * i + 1];
        #pragma unroll
        for (int ct = 0; ct < 8; ct++) {
            const int c0 = cq * 64 + ct * 8 + t4 * 2;
            const int oi = i * 8 + ct;
            ob[(size_t)c0 * L_ + mA]       = o[oi][0] * iA + xb[(size_t)c0 * L_ + mA];
            ob[(size_t)(c0 + 1) * L_ + mA] = o[oi][1] * iA + xb[(size_t)(c0 + 1) * L_ + mA];
            ob[(size_t)c0 * L_ + mB]       = o[oi][2] * iB + xb[(size_t)c0 * L_ + mB];
            ob[(size_t)(c0 + 1) * L_ + mB] = o[oi][3] * iB + xb[(size_t)(c0 + 1) * L_ + mB];
        }
    }
}

// ---------------------------------------------------------------------------
extern "C" void kernel_launch(void* const* d_in, const int* in_sizes, int n_in,
                              void* d_out, int out_size)
{
    (void)in_sizes; (void)n_in; (void)out_size;
    const float* x     = (const float*)d_in[0];
    const float* Wq    = (const float*)d_in[1];
    const float* bq    = (const float*)d_in[2];
    const float* Wk    = (const float*)d_in[3];
    const float* bk    = (const float*)d_in[4];
    const float* Wv    = (const float*)d_in[5];
    const float* bv    = (const float*)d_in[6];
    const float* gamma = (const float*)d_in[7];
    float* out = (float*)d_out;

    conv_w_kernel<<<320, 256>>>(Wq, bq, Wk, bk, Wv, bv);
    conv_x_kernel<<<2048, 256>>>(x);

    cudaFuncSetAttribute(proj_kernel, cudaFuncAttributeMaxDynamicSharedMemorySize, SMEM_PROJ);
    proj_kernel<<<dim3(L_ / 128, 5, B_), 256, SMEM_PROJ>>>();

    cudaFuncSetAttribute(attn_kernel, cudaFuncAttributeMaxDynamicSharedMemorySize, SMEM_AT);
    attn_kernel<<<dim3(L_ / 64, B_), 256, SMEM_AT>>>(x, gamma, out);
}

// round 16
// speedup vs baseline: 1.4807x; 1.0460x over previous
#include <cuda_runtime.h>
#include <cuda_bf16.h>
#include <cstdint>

#define B_ 8
#define C_ 256
#define L_ 2048
#define D_ 32
#define LOG2E 1.4426950408889634f

// scratch: bf16 inputs + projections (q pre-scaled by log2(e))
__device__ __nv_bfloat16 g_wb[320 * 256];             // [r][c] bf16 (Wq*log2e | Wk | Wv)
__device__ float         g_bias[320];                 // bq*log2e | bk | bv
__device__ __nv_bfloat16 g_xb[(size_t)B_ * C_ * L_];  // [b][c][l] bf16
__device__ __nv_bfloat16 g_q[(size_t)B_ * L_ * D_];   // [b][l][32] bf16
__device__ __nv_bfloat16 g_k[(size_t)B_ * L_ * D_];   // [b][l][32] bf16
__device__ __nv_bfloat16 g_v[(size_t)B_ * C_ * L_];   // [b][c][l]  bf16

// ---------------------------------------------------------------------------
// helpers
// ---------------------------------------------------------------------------
__device__ __forceinline__ uint32_t smem_u32(const void* p) {
    uint32_t a;
    asm("{ .reg .u64 t; cvta.to.shared.u64 t, %1; cvt.u32.u64 %0, t; }" : "=r"(a) : "l"(p));
    return a;
}
#define CP16(dst, src) \
    asm volatile("cp.async.cg.shared.global [%0], [%1], 16;" :: "r"(dst), "l"(src))
#define CP_COMMIT() asm volatile("cp.async.commit_group;")
#define CP_WAIT(n)  asm volatile("cp.async.wait_group %0;" :: "n"(n))

#define CVT_BF16X2_F32(result, a, b) \
    asm("cvt.rn.satfinite.bf16x2.f32 %0, %1, %2;" : "=r"(result) : "f"(b), "f"(a))

#define EX2F(d, s) asm("ex2.approx.f32 %0, %1;" : "=f"(d) : "f"(s))

#define STS32(addr, val) \
    asm volatile("st.shared.b32 [%0], %1;" :: "r"(addr), "r"(val) : "memory")

#define NAMED_BAR(id, cnt) \
    asm volatile("bar.sync %0, %1;" :: "r"(id), "r"(cnt) : "memory")

#define LDMATRIX_X4(r0, r1, r2, r3, addr) \
    asm volatile("ldmatrix.sync.aligned.m8n8.x4.shared.b16 {%0,%1,%2,%3}, [%4];" \
        : "=r"(r0), "=r"(r1), "=r"(r2), "=r"(r3) : "r"(addr))

#define LDMATRIX_X4_T(r0, r1, r2, r3, addr) \
    asm volatile("ldmatrix.sync.aligned.m8n8.x4.trans.shared.b16 {%0,%1,%2,%3}, [%4];" \
        : "=r"(r0), "=r"(r1), "=r"(r2), "=r"(r3) : "r"(addr))

#define MMA_BF16(d0,d1,d2,d3,a0,a1,a2,a3,b0,b1) \
    asm volatile("mma.sync.aligned.m16n8k16.row.col.f32.bf16.bf16.f32 " \
        "{%0,%1,%2,%3}, {%4,%5,%6,%7}, {%8,%9}, {%0,%1,%2,%3};" \
        : "+f"(d0), "+f"(d1), "+f"(d2), "+f"(d3) \
        : "r"(a0), "r"(a1), "r"(a2), "r"(a3), "r"(b0), "r"(b1))

// ---------------------------------------------------------------------------
// Kernel 0: convert x and W (+fold log2e into Wq/bq) to bf16 in one launch.
// blocks 0..2047: x (8 elems/thread); blocks 2048..2367: W rows.
// ---------------------------------------------------------------------------
__global__ __launch_bounds__(256) void conv_kernel(
    const float* __restrict__ x,
    const float* __restrict__ Wq, const float* __restrict__ bq,
    const float* __restrict__ Wk, const float* __restrict__ bk,
    const float* __restrict__ Wv, const float* __restrict__ bv)
{
    const int bid = blockIdx.x;
    const int tid = threadIdx.x;
    if (bid < 2048) {
        const size_t base = (size_t)bid * 2048 + tid * 8;
        float4 a = *(const float4*)(x + base);
        float4 b = *(const float4*)(x + base + 4);
        uint4 o;
        CVT_BF16X2_F32(o.x, a.x, a.y);
        CVT_BF16X2_F32(o.y, a.z, a.w);
        CVT_BF16X2_F32(o.z, b.x, b.y);
        CVT_BF16X2_F32(o.w, b.z, b.w);
        *(uint4*)(g_xb + base) = o;
    } else {
        const int r = bid - 2048;
        const float* src;
        float bias, sc;
        if (r < D_)          { src = Wq + (size_t)r * C_;            bias = bq[r];          sc = LOG2E; }
        else if (r < 2 * D_) { src = Wk + (size_t)(r - D_) * C_;     bias = bk[r - D_];     sc = 1.f;  }
        else                 { src = Wv + (size_t)(r - 2 * D_) * C_; bias = bv[r - 2 * D_]; sc = 1.f;  }
        g_wb[(size_t)r * C_ + tid] = __float2bfloat16_rn(src[tid] * sc);
        if (tid == 0) g_bias[r] = bias * sc;
    }
}

// ---------------------------------------------------------------------------
// Kernel 1: QKV projection via bf16 mma.sync, ldmatrix fragments.
//   A = W bf16 [r][c] (k-major, normal ldmatrix);
//   B = x bf16 [c][l] (k-row-major, ldmatrix.trans).
// Block: 64 r x 128 l, 256 threads = 8 warps (4 m-tiles x 2 l-halves of 64).
// k=256 in 8 chunks of 32, double-buffered. Grid (16, 5, 8), 3 blocks/SM.
// SMEM: sW 2x[64][80B] | sX 2x[32][272B]  (27.6 KB)
// ---------------------------------------------------------------------------
#define WROW 80
#define XROW 272
#define PJW_OFF 0
#define PJW_B   (64 * WROW)               // 5120
#define PJX_OFF (2 * PJW_B)               // 10240
#define PJX_B   (32 * XROW)               // 8704
#define SMEM_PROJ (PJX_OFF + 2 * PJX_B)   // 27648

__global__ __launch_bounds__(256, 3) void proj_kernel()
{
    extern __shared__ char smem[];
    const uint32_t sb = smem_u32(smem);

    const int b  = blockIdx.z;
    const int r0 = blockIdx.y * 64;
    const int l0 = blockIdx.x * 128;
    const int tid  = threadIdx.x;
    const int lane = tid & 31;
    const int w    = tid >> 5;
    const int g    = lane >> 2;
    const int t4   = lane & 3;
    const int mb   = (w & 3) * 16;
    const int lw   = (w >> 2) * 64;
    const int lr   = lane & 7;
    const int l8   = (lane >> 3) & 1;
    const int l16  = (lane >> 4) & 1;

    const __nv_bfloat16* xg = g_xb + (size_t)b * C_ * L_;

    auto load_w = [&](int ck) {            // W chunk ck (32 c) -> wbuf ck&1
        int row = tid >> 2, seg = tid & 3; // 64 rows x 4 segs of 16B
        CP16(sb + PJW_OFF + (ck & 1) * PJW_B + row * WROW + seg * 16,
             g_wb + (size_t)(r0 + row) * C_ + ck * 32 + seg * 8);
    };
    auto load_x = [&](int ck) {            // X chunk ck (32 c x 128 l) -> xbuf ck&1
        #pragma unroll
        for (int t = 0; t < 2; t++) {
            int idx = tid + t * 256;       // 512 = 32 rows x 16 segs of 16B
            int row = idx >> 4, seg = idx & 15;
            CP16(sb + PJX_OFF + (ck & 1) * PJX_B + row * XROW + seg * 16,
                 xg + (size_t)(ck * 32 + row) * L_ + l0 + seg * 8);
        }
    };

    load_w(0);
    load_x(0);
    CP_COMMIT();

    // ldmatrix base addresses
    const uint32_t wlm = sb + PJW_OFF + (uint32_t)(mb + lr + l8 * 8) * WROW + l16 * 16;
    const uint32_t xlm = sb + PJX_OFF + (uint32_t)(lr + l8 * 8) * XROW
                       + (uint32_t)(lw + l16 * 8) * 2;

    const int r_g  = r0 + mb + g;
    const int r_g8 = r_g + 8;
    const float bias_lo = g_bias[r_g];
    const float bias_hi = g_bias[r_g8];
    float o[8][4];
    #pragma unroll
    for (int nt = 0; nt < 8; nt++) {
        o[nt][0] = bias_lo; o[nt][1] = bias_lo;
        o[nt][2] = bias_hi; o[nt][3] = bias_hi;
    }

    for (int ck = 0; ck < 8; ck++) {
        const int buf = ck & 1;
        CP_WAIT(0);
        __syncthreads();
        if (ck < 7) {
            load_w(ck + 1);
            load_x(ck + 1);
            CP_COMMIT();
        }
        const uint32_t wb = wlm + buf * PJW_B;
        const uint32_t xbm = xlm + buf * PJX_B;
        #pragma unroll
        for (int s01 = 0; s01 < 2; s01++) {
            uint32_t a0, a1, a2, a3;
            LDMATRIX_X4(a0, a1, a2, a3, wb + s01 * 32);
            #pragma unroll
            for (int np = 0; np < 4; np++) {
                uint32_t b0, b1, b2, b3;
                LDMATRIX_X4_T(b0, b1, b2, b3,
                              xbm + s01 * (16 * XROW) + np * 32);
                MMA_BF16(o[2*np][0], o[2*np][1], o[2*np][2], o[2*np][3],
                         a0, a1, a2, a3, b0, b1);
                MMA_BF16(o[2*np+1][0], o[2*np+1][1], o[2*np+1][2], o[2*np+1][3],
                         a0, a1, a2, a3, b2, b3);
            }
        }
    }

    if (r_g < 2 * D_) {
        const bool isq = (r_g < D_);
        __nv_bfloat16* dst = isq ? (g_q + (size_t)b * L_ * D_)
                                 : (g_k + (size_t)b * L_ * D_);
        const int d  = isq ? r_g : (r_g - D_);
        const int d8 = d + 8;
        #pragma unroll
        for (int nt = 0; nt < 8; nt++) {
            const int l = l0 + lw + nt * 8 + t4 * 2;
            dst[(size_t)l * D_ + d]        = __float2bfloat16_rn(o[nt][0]);
            dst[(size_t)(l + 1) * D_ + d]  = __float2bfloat16_rn(o[nt][1]);
            dst[(size_t)l * D_ + d8]       = __float2bfloat16_rn(o[nt][2]);
            dst[(size_t)(l + 1) * D_ + d8] = __float2bfloat16_rn(o[nt][3]);
        }
    } else {
        __nv_bfloat16* vb = g_v + (size_t)b * C_ * L_;
        const int c = r_g - 2 * D_, c8 = c + 8;
        #pragma unroll
        for (int nt = 0; nt < 8; nt++) {
            const int l = l0 + lw + nt * 8 + t4 * 2;
            uint32_t lo, hi;
            CVT_BF16X2_F32(lo, o[nt][0], o[nt][1]);
            CVT_BF16X2_F32(hi, o[nt][2], o[nt][3]);
            *(uint32_t*)&vb[(size_t)c * L_ + l]  = lo;
            *(uint32_t*)&vb[(size_t)c8 * L_ + l] = hi;
        }
    }
}

// ---------------------------------------------------------------------------
// Kernel 2: bf16 mma.sync flash attention (R13 structure + micro-pipelining):
//   - both K ldmatrix loads hoisted to stage-A start
//   - stage-B V fragments ping-ponged (prefetch next before current MMAs)
//   - K/V cp.async prefetch issued after stage A
// 64 q x 256 c blocks, 256 threads = 8 warps (2 m-groups x 4 c-quarters).
// SMEM: sQ [64][80B] | sK 2x[64][80B] | sV 2x[256][144B] | sP 2x[32][144B] | sRS
// ---------------------------------------------------------------------------
#define QKROW 80
#define VROW  144
#define SQ_OFF  0
#define SK_OFF  5120
#define SKB     5120
#define SV_OFF  15360
#define SVB     36864
#define SP_OFF  89088
#define SPM     4608                   // 32 rows x 144 B per m-group
#define SRS_OFF 98304                  // 64 rows x 4 cq floats = 1024 B
#define SMEM_AT 99328

__global__ __launch_bounds__(256, 2) void attn_kernel(
    const float* __restrict__ x, const float* __restrict__ gamma_p,
    float* __restrict__ out)
{
    extern __shared__ char smem[];
    const uint32_t sb = smem_u32(smem);

    const int tid  = threadIdx.x;
    const int lane = tid & 31;
    const int w    = tid >> 5;
    const int g    = lane >> 2;
    const int t4   = lane & 3;
    const int mgrp = w >> 2;           // 0/1 : q rows mgrp*32..+31 (warps 0-3 / 4-7)
    const int cq   = w & 3;            // 0..3 : c cols cq*64..+63
    const int lr   = lane & 7;
    const int l8   = (lane >> 3) & 1;
    const int l16  = (lane >> 4) & 1;

    const int b  = blockIdx.y;
    const int m0 = blockIdx.x * 64;

    const __nv_bfloat16* qg = g_q + (size_t)b * L_ * D_;
    const __nv_bfloat16* kg = g_k + (size_t)b * L_ * D_;
    const __nv_bfloat16* vg = g_v + (size_t)b * C_ * L_;

    // ---- ldmatrix / STS base addresses ----
    const uint32_t qlm  = sb + SQ_OFF + (uint32_t)(mgrp * 32 + lr + l8 * 8) * QKROW + l16 * 16;
    const uint32_t klmb = sb + SK_OFF + (uint32_t)(16 * cq + lr) * QKROW + (lane >> 3) * 16;
    const uint32_t vlmb = sb + SV_OFF + (uint32_t)(cq * 64 + l16 * 8 + lr) * VROW + l8 * 16;
    const uint32_t plm  = sb + SP_OFF + mgrp * SPM + (uint32_t)(lr + l8 * 8) * VROW + l16 * 16;
    const uint32_t psta = sb + SP_OFF + mgrp * SPM + (uint32_t)g * VROW + (16 * cq + 2 * t4) * 2;

    // ---- preload Q (64x32), K0, V0 ----
    {
        int row = tid >> 2, seg = tid & 3;
        CP16(sb + SQ_OFF + row * QKROW + seg * 16, qg + (size_t)(m0 + row) * D_ + seg * 8);
        CP16(sb + SK_OFF + row * QKROW + seg * 16, kg + (size_t)row * D_ + seg * 8);
        #pragma unroll
        for (int t = 0; t < 8; t++) {
            int idx = tid + t * 256;
            int r = idx >> 3, s = idx & 7;
            CP16(sb + SV_OFF + r * VROW + s * 16, vg + (size_t)r * L_ + s * 8);
        }
        CP_COMMIT();
    }

    uint32_t qa[2][8];                 // 2 m-tiles x (k0-15: 4, k16-31: 4)
    float o[16][4];                    // [i*8 + ct2][4]
    #pragma unroll
    for (int i = 0; i < 16; i++)
        #pragma unroll
        for (int j = 0; j < 4; j++) o[i][j] = 0.f;
    float rs[4] = {0.f, 0.f, 0.f, 0.f};   // rows: i0 g, i0 g+8, i1 g, i1 g+8

    for (int it = 0; it < 32; it++) {
        const int buf = it & 1;
        CP_WAIT(0);
        __syncthreads();

        if (it == 0) {
            #pragma unroll
            for (int i = 0; i < 2; i++) {
                LDMATRIX_X4(qa[i][0], qa[i][1], qa[i][2], qa[i][3],
                            qlm + i * (16 * QKROW));
                LDMATRIX_X4(qa[i][4], qa[i][5], qa[i][6], qa[i][7],
                            qlm + i * (16 * QKROW) + 32);
            }
        }

        const uint32_t klm = klmb + buf * SKB;
        const uint32_t vlm = vlmb + buf * SVB;

        // ---- stage A: S(32q x 16 keys of quarter cq), ex2, pack -> sP ----
        {
            uint32_t kb[2][4];
            LDMATRIX_X4(kb[0][0], kb[0][1], kb[0][2], kb[0][3], klm);
            LDMATRIX_X4(kb[1][0], kb[1][1], kb[1][2], kb[1][3], klm + 8 * QKROW);
            #pragma unroll
            for (int t = 0; t < 2; t++) {
                #pragma unroll
                for (int i = 0; i < 2; i++) {
                    float d0 = 0.f, d1 = 0.f, d2 = 0.f, d3 = 0.f;
                    MMA_BF16(d0, d1, d2, d3,
                             qa[i][0], qa[i][1], qa[i][2], qa[i][3], kb[t][0], kb[t][1]);
                    MMA_BF16(d0, d1, d2, d3,
                             qa[i][4], qa[i][5], qa[i][6], qa[i][7], kb[t][2], kb[t][3]);
                    float e0, e1, e2, e3;
                    EX2F(e0, d0); EX2F(e1, d1); EX2F(e2, d2); EX2F(e3, d3);
                    rs[2 * i]     += e0 + e1;
                    rs[2 * i + 1] += e2 + e3;
                    uint32_t lo, hi;
                    CVT_BF16X2_F32(lo, e0, e1);
                    CVT_BF16X2_F32(hi, e2, e3);
                    STS32(psta + i * (16 * VROW) + t * 16, lo);
                    STS32(psta + i * (16 * VROW) + 8 * VROW + t * 16, hi);
                }
            }
        }

        // ---- prefetch K,V chunk it+1 (after stage A, before named bar) ----
        if (it < 31) {
            const int n1 = (it + 1) * 64;
            const int pb = (it + 1) & 1;
            int row = tid >> 2, seg = tid & 3;
            CP16(sb + SK_OFF + pb * SKB + row * QKROW + seg * 16,
                 kg + (size_t)(n1 + row) * D_ + seg * 8);
            #pragma unroll
            for (int t = 0; t < 8; t++) {
                int idx = tid + t * 256;
                int r = idx >> 3, s = idx & 7;
                CP16(sb + SV_OFF + pb * SVB + r * VROW + s * 16,
                     vg + (size_t)r * L_ + n1 + s * 8);
            }
            CP_COMMIT();
        }

        // per-m-group sync: P producers == P consumers == warps of this mgrp
        NAMED_BAR(1 + mgrp, 128);

        // ---- stage B: O += P Vt, V fragments ping-ponged ----
        {
            uint32_t v[2][4];
            LDMATRIX_X4(v[0][0], v[0][1], v[0][2], v[0][3], vlm);
            #pragma unroll
            for (int j = 0; j < 4; j++) {
                uint32_t a0[4], a1[4];
                LDMATRIX_X4(a0[0], a0[1], a0[2], a0[3], plm + j * 32);
                LDMATRIX_X4(a1[0], a1[1], a1[2], a1[3], plm + 16 * VROW + j * 32);
                #pragma unroll
                for (int cp = 0; cp < 4; cp++) {
                    const int cur = (j * 4 + cp) & 1;
                    const int nxt = cur ^ 1;
                    if (!(j == 3 && cp == 3)) {
                        const int nj  = (cp == 3) ? j + 1 : j;
                        const int ncp = (cp + 1) & 3;
                        LDMATRIX_X4(v[nxt][0], v[nxt][1], v[nxt][2], v[nxt][3],
                                    vlm + ncp * (16 * VROW) + nj * 32);
                    }
                    MMA_BF16(o[2*cp][0], o[2*cp][1], o[2*cp][2], o[2*cp][3],
                             a0[0], a0[1], a0[2], a0[3], v[cur][0], v[cur][1]);
                    MMA_BF16(o[2*cp+1][0], o[2*cp+1][1], o[2*cp+1][2], o[2*cp+1][3],
                             a0[0], a0[1], a0[2], a0[3], v[cur][2], v[cur][3]);
                    MMA_BF16(o[8+2*cp][0], o[8+2*cp][1], o[8+2*cp][2], o[8+2*cp][3],
                             a1[0], a1[1], a1[2], a1[3], v[cur][0], v[cur][1]);
                    MMA_BF16(o[8+2*cp+1][0], o[8+2*cp+1][1], o[8+2*cp+1][2], o[8+2*cp+1][3],
                             a1[0], a1[1], a1[2], a1[3], v[cur][2], v[cur][3]);
                }
            }
        }
    }

    // ---- rowsums: t4 shfl reduce, then combine 4 c-quarters via smem ----
    #pragma unroll
    for (int r = 0; r < 4; r++) {
        rs[r] += __shfl_xor_sync(0xFFFFFFFFu, rs[r], 1);
        rs[r] += __shfl_xor_sync(0xFFFFFFFFu, rs[r], 2);
    }
    float* sRS = (float*)(smem + SRS_OFF);
    if (t4 == 0) {
        sRS[(mgrp * 32 + g) * 4 + cq]           = rs[0];
        sRS[(mgrp * 32 + g + 8) * 4 + cq]       = rs[1];
        sRS[(mgrp * 32 + 16 + g) * 4 + cq]      = rs[2];
        sRS[(mgrp * 32 + 16 + g + 8) * 4 + cq]  = rs[3];
    }
    __syncthreads();

    const float gam = gamma_p[0];
    float inv[4];
    #pragma unroll
    for (int r = 0; r < 4; r++) {
        const int row = mgrp * 32 + 16 * (r >> 1) + (r & 1) * 8 + g;
        inv[r] = gam / (sRS[row * 4] + sRS[row * 4 + 1] + sRS[row * 4 + 2] + sRS[row * 4 + 3]);
    }

    const float* xb = x + (size_t)b * C_ * L_;
    float* ob = out + (size_t)b * C_ * L_;
    #pragma unroll
    for (int i = 0; i < 2; i++) {
        const int mA = m0 + mgrp * 32 + 16 * i + g;
        const int mB = mA + 8;
        const float iA = inv[2 * i], iB = inv[2 * i + 1];
        #pragma unroll
        for (int ct = 0; ct < 8; ct++) {
            const int c0 = cq * 64 + ct * 8 + t4 * 2;
            const int oi = i * 8 + ct;
            ob[(size_t)c0 * L_ + mA]       = o[oi][0] * iA + xb[(size_t)c0 * L_ + mA];
            ob[(size_t)(c0 + 1) * L_ + mA] = o[oi][1] * iA + xb[(size_t)(c0 + 1) * L_ + mA];
            ob[(size_t)c0 * L_ + mB]       = o[oi][2] * iB + xb[(size_t)c0 * L_ + mB];
            ob[(size_t)(c0 + 1) * L_ + mB] = o[oi][3] * iB + xb[(size_t)(c0 + 1) * L_ + mB];
        }
    }
}

// ---------------------------------------------------------------------------
extern "C" void kernel_launch(void* const* d_in, const int* in_sizes, int n_in,
                              void* d_out, int out_size)
{
    (void)in_sizes; (void)n_in; (void)out_size;
    const float* x     = (const float*)d_in[0];
    const float* Wq    = (const float*)d_in[1];
    const float* bq    = (const float*)d_in[2];
    const float* Wk    = (const float*)d_in[3];
    const float* bk    = (const float*)d_in[4];
    const float* Wv    = (const float*)d_in[5];
    const float* bv    = (const float*)d_in[6];
    const float* gamma = (const float*)d_in[7];
    float* out = (float*)d_out;

    conv_kernel<<<2368, 256>>>(x, Wq, bq, Wk, bk, Wv, bv);

    cudaFuncSetAttribute(proj_kernel, cudaFuncAttributeMaxDynamicSharedMemorySize, SMEM_PROJ);
    proj_kernel<<<dim3(L_ / 128, 5, B_), 256, SMEM_PROJ>>>();

    cudaFuncSetAttribute(attn_kernel, cudaFuncAttributeMaxDynamicSharedMemorySize, SMEM_AT);
    attn_kernel<<<dim3(L_ / 64, B_), 256, SMEM_AT>>>(x, gamma, out);
}